// round 1
// baseline (speedup 1.0000x reference)
#include <cuda_runtime.h>

#define NN 50000
#define NE 800000
#define EPSB 1e-5f

#define TR 128           // rows per tile
#define TK 64            // K depth
#define SA 129           // A_s row stride (odd -> conflict-free STS/LDS)
#define NT 256           // threads per block
#define SMEM_FLOATS (TK*SA + 64*64)
#define SMEM_BYTES  (SMEM_FLOATS * 4)   // 49408 B

// ---------------- scratch (device globals; no allocs allowed) ----------------
__device__ __align__(16) float g_xw1m[NN * 64];     // x @ w1m[:64] + b1m
__device__ __align__(16) float g_xw1n[NN * 64];     // x @ w1n[:64] + b1n
__device__ __align__(16) float g_h1[51200000];      // edge pre-BN activations [E,64]
__device__ __align__(16) float g_hn[NN * 64];       // node pre-BN activations
__device__ __align__(16) float g_agg[NN * 64];      // scatter sums
__device__ float g_inv[NN];                         // 1/max(cnt,1)
__device__ int   g_cnt[NN];
__device__ float g_stats[256];   // [0:64) sumM [64:128) ssM [128:192) sumN [192:256) ssN
__device__ float g_coef[256];    // [0:64) scaleM [64:128) shiftM [128..] scaleN shiftN

// ---------------- helpers ----------------
__device__ __forceinline__ void red_add4(float* p, float x, float y, float z, float w) {
    asm volatile("red.global.add.v4.f32 [%0], {%1,%2,%3,%4};"
                 :: "l"(p), "f"(x), "f"(y), "f"(z), "f"(w) : "memory");
}

__device__ __forceinline__ void load_W(const float* __restrict__ W, float* W_s, int tid) {
    const float4* wg = reinterpret_cast<const float4*>(W);
    float4* ws = reinterpret_cast<float4*>(W_s);
#pragma unroll
    for (int j = 0; j < 4; ++j) ws[tid + j * NT] = wg[tid + j * NT];
}

__device__ __forceinline__ void mm64(const float* __restrict__ A_s,
                                     const float* __restrict__ W_s,
                                     int rg, int c4, float acc[8][4]) {
#pragma unroll 8
    for (int k = 0; k < TK; ++k) {
        const float4 b = *reinterpret_cast<const float4*>(W_s + k * 64 + c4 * 4);
        const float* ar = A_s + k * SA + rg * 8;
#pragma unroll
        for (int i = 0; i < 8; ++i) {
            const float a = ar[i];
            acc[i][0] = fmaf(a, b.x, acc[i][0]);
            acc[i][1] = fmaf(a, b.y, acc[i][1]);
            acc[i][2] = fmaf(a, b.z, acc[i][2]);
            acc[i][3] = fmaf(a, b.w, acc[i][3]);
        }
    }
}

#define ZERO_ACC(acc) do { \
    _Pragma("unroll") for (int _i = 0; _i < 8; ++_i) { \
        acc[_i][0]=0.f; acc[_i][1]=0.f; acc[_i][2]=0.f; acc[_i][3]=0.f; } } while (0)

// ---------------- small kernels ----------------
__global__ void k_zero() {
    int i = blockIdx.x * blockDim.x + threadIdx.x;
    if (i < NN * 64) g_agg[i] = 0.f;
    if (i < NN)      g_cnt[i] = 0;
    if (i < 256)     g_stats[i] = 0.f;
}

__global__ void k_count(const int* __restrict__ ei) {
    int i = blockIdx.x * blockDim.x + threadIdx.x;
    if (i < NE) atomicAdd(&g_cnt[ei[NE + i]], 1);
}

__global__ void k_inv() {
    int i = blockIdx.x * blockDim.x + threadIdx.x;
    if (i < NN) g_inv[i] = 1.0f / fmaxf((float)g_cnt[i], 1.0f);
}

// column sums + sums of squares over [R,64] matrix
__global__ void k_stats(const float* __restrict__ h, int R, int off) {
    const int col = threadIdx.x & 63;
    const int sub = threadIdx.x >> 6;
    float s = 0.f, ss = 0.f;
    for (int r = blockIdx.x * 4 + sub; r < R; r += gridDim.x * 4) {
        float v = h[(long long)r * 64 + col];
        s += v;
        ss = fmaf(v, v, ss);
    }
    __shared__ float red[512];
    red[threadIdx.x] = s;
    red[256 + threadIdx.x] = ss;
    __syncthreads();
    if (threadIdx.x < 64) {
        s  = red[col] + red[col + 64] + red[col + 128] + red[col + 192];
        ss = red[256 + col] + red[256 + col + 64] + red[256 + col + 128] + red[256 + col + 192];
        atomicAdd(&g_stats[off + col], s);
        atomicAdd(&g_stats[off + 64 + col], ss);
    }
}

__global__ void k_coef(int off, float invR,
                       const float* __restrict__ gamma, const float* __restrict__ beta) {
    int c = threadIdx.x;  // 64 threads
    float mean = g_stats[off + c] * invR;
    float ms   = g_stats[off + 64 + c] * invR;
    float var  = ms - mean * mean;
    float sc   = gamma[c] * rsqrtf(var + EPSB);
    g_coef[off + c]      = sc;
    g_coef[off + 64 + c] = beta[c] - mean * sc;
}

// ---------------- tile GEMM kernels ----------------
// out[r] = A[r] @ W + bias  (generic, guarded)
__global__ void k_gemm_bias(const float* __restrict__ A, int R,
                            const float* __restrict__ W,
                            const float* __restrict__ bias,
                            float* __restrict__ out) {
    extern __shared__ float smem[];
    float* A_s = smem;
    float* W_s = smem + TK * SA;
    const int tid = threadIdx.x;
    const int base = blockIdx.x * TR;
    load_W(W, W_s, tid);
#pragma unroll
    for (int j = 0; j < 32; ++j) {
        int idx = tid + j * NT;
        int k = idx & 63, row = idx >> 6;
        int r = base + row; if (r > R - 1) r = R - 1;
        A_s[k * SA + row] = A[r * 64 + k];
    }
    __syncthreads();
    const int c4 = tid & 15, rg = tid >> 4;
    float acc[8][4];
    ZERO_ACC(acc);
    mm64(A_s, W_s, rg, c4, acc);
    const float4 bb = *reinterpret_cast<const float4*>(bias + c4 * 4);
#pragma unroll
    for (int i = 0; i < 8; ++i) {
        int r = base + rg * 8 + i;
        if (r < R) {
            float4 v = make_float4(acc[i][0] + bb.x, acc[i][1] + bb.y,
                                   acc[i][2] + bb.z, acc[i][3] + bb.w);
            *reinterpret_cast<float4*>(out + r * 64 + c4 * 4) = v;
        }
    }
}

// h1[e] = edge_attr[e] @ w1m[64:] + (x@w1m[:64]+b1m)[send[e]]   (E % TR == 0)
__global__ void k_edge1(const float* __restrict__ ea,
                        const int* __restrict__ ei,
                        const float* __restrict__ Wbot) {
    extern __shared__ float smem[];
    float* A_s = smem;
    float* W_s = smem + TK * SA;
    const int tid = threadIdx.x;
    const int base = blockIdx.x * TR;
    load_W(Wbot, W_s, tid);
#pragma unroll
    for (int j = 0; j < 32; ++j) {
        int idx = tid + j * NT;
        int k = idx & 63, row = idx >> 6;
        int r = base + row;
        A_s[k * SA + row] = ea[(long long)r * 64 + k];
    }
    __syncthreads();
    const int c4 = tid & 15, rg = tid >> 4;
    float acc[8][4];
    ZERO_ACC(acc);
    mm64(A_s, W_s, rg, c4, acc);
#pragma unroll
    for (int i = 0; i < 8; ++i) {
        int r = base + rg * 8 + i;
        int s = ei[r];  // sender node
        float4 xw = *reinterpret_cast<const float4*>(g_xw1m + s * 64 + c4 * 4);
        float4 v = make_float4(acc[i][0] + xw.x, acc[i][1] + xw.y,
                               acc[i][2] + xw.z, acc[i][3] + xw.w);
        *reinterpret_cast<float4*>(g_h1 + (long long)r * 64 + c4 * 4) = v;
    }
}

// m = relu(h1*scale+shift) @ w2m + b2m ; scatter-add into g_agg[rec]
__global__ void k_edge2(const int* __restrict__ ei,
                        const float* __restrict__ W2,
                        const float* __restrict__ b2) {
    extern __shared__ float smem[];
    float* A_s = smem;
    float* W_s = smem + TK * SA;
    const int tid = threadIdx.x;
    const int base = blockIdx.x * TR;
    load_W(W2, W_s, tid);
    const float cs = g_coef[tid & 63];
    const float ch = g_coef[64 + (tid & 63)];
#pragma unroll
    for (int j = 0; j < 32; ++j) {
        int idx = tid + j * NT;
        int k = idx & 63, row = idx >> 6;
        int r = base + row;
        float v = fmaf(g_h1[(long long)r * 64 + k], cs, ch);
        A_s[k * SA + row] = fmaxf(v, 0.f);
    }
    __syncthreads();
    const int c4 = tid & 15, rg = tid >> 4;
    float acc[8][4];
    ZERO_ACC(acc);
    mm64(A_s, W_s, rg, c4, acc);
    const float4 bb = *reinterpret_cast<const float4*>(b2 + c4 * 4);
#pragma unroll
    for (int i = 0; i < 8; ++i) {
        int r = base + rg * 8 + i;
        int rec = ei[NE + r];  // receiver node
        red_add4(g_agg + rec * 64 + c4 * 4,
                 acc[i][0] + bb.x, acc[i][1] + bb.y,
                 acc[i][2] + bb.z, acc[i][3] + bb.w);
    }
}

// hn[i] = (agg[i]*inv[i]) @ w1n[64:] + (x@w1n[:64]+b1n)[i]
__global__ void k_node1(const float* __restrict__ Wbot) {
    extern __shared__ float smem[];
    float* A_s = smem;
    float* W_s = smem + TK * SA;
    const int tid = threadIdx.x;
    const int base = blockIdx.x * TR;
    load_W(Wbot, W_s, tid);
#pragma unroll
    for (int j = 0; j < 32; ++j) {
        int idx = tid + j * NT;
        int k = idx & 63, row = idx >> 6;
        int r = base + row; if (r > NN - 1) r = NN - 1;
        A_s[k * SA + row] = g_agg[r * 64 + k] * g_inv[r];
    }
    __syncthreads();
    const int c4 = tid & 15, rg = tid >> 4;
    float acc[8][4];
    ZERO_ACC(acc);
    mm64(A_s, W_s, rg, c4, acc);
#pragma unroll
    for (int i = 0; i < 8; ++i) {
        int r = base + rg * 8 + i;
        if (r < NN) {
            float4 xw = *reinterpret_cast<const float4*>(g_xw1n + r * 64 + c4 * 4);
            float4 v = make_float4(acc[i][0] + xw.x, acc[i][1] + xw.y,
                                   acc[i][2] + xw.z, acc[i][3] + xw.w);
            *reinterpret_cast<float4*>(g_hn + r * 64 + c4 * 4) = v;
        }
    }
}

// out = relu(hn*scaleN+shiftN) @ w2n + b2n
__global__ void k_node2(const float* __restrict__ W2,
                        const float* __restrict__ b2,
                        float* __restrict__ out) {
    extern __shared__ float smem[];
    float* A_s = smem;
    float* W_s = smem + TK * SA;
    const int tid = threadIdx.x;
    const int base = blockIdx.x * TR;
    load_W(W2, W_s, tid);
    const float cs = g_coef[128 + (tid & 63)];
    const float ch = g_coef[192 + (tid & 63)];
#pragma unroll
    for (int j = 0; j < 32; ++j) {
        int idx = tid + j * NT;
        int k = idx & 63, row = idx >> 6;
        int r = base + row; if (r > NN - 1) r = NN - 1;
        float v = fmaf(g_hn[r * 64 + k], cs, ch);
        A_s[k * SA + row] = fmaxf(v, 0.f);
    }
    __syncthreads();
    const int c4 = tid & 15, rg = tid >> 4;
    float acc[8][4];
    ZERO_ACC(acc);
    mm64(A_s, W_s, rg, c4, acc);
    const float4 bb = *reinterpret_cast<const float4*>(b2 + c4 * 4);
#pragma unroll
    for (int i = 0; i < 8; ++i) {
        int r = base + rg * 8 + i;
        if (r < NN) {
            float4 v = make_float4(acc[i][0] + bb.x, acc[i][1] + bb.y,
                                   acc[i][2] + bb.z, acc[i][3] + bb.w);
            *reinterpret_cast<float4*>(out + r * 64 + c4 * 4) = v;
        }
    }
}

// ---------------- launch ----------------
extern "C" void kernel_launch(void* const* d_in, const int* in_sizes, int n_in,
                              void* d_out, int out_size) {
    const float* x   = (const float*)d_in[0];
    const int*   ei  = (const int*)d_in[1];
    const float* ea  = (const float*)d_in[2];
    // d_in[3]=u, d_in[4]=batch : unused by the reference output
    const float* w1m = (const float*)d_in[5];
    const float* b1m = (const float*)d_in[6];
    const float* gm  = (const float*)d_in[7];
    const float* bm  = (const float*)d_in[8];
    const float* w2m = (const float*)d_in[9];
    const float* b2m = (const float*)d_in[10];
    const float* w1n = (const float*)d_in[11];
    const float* b1n = (const float*)d_in[12];
    const float* gn  = (const float*)d_in[13];
    const float* bn  = (const float*)d_in[14];
    const float* w2n = (const float*)d_in[15];
    const float* b2n = (const float*)d_in[16];
    float* out = (float*)d_out;

    cudaFuncSetAttribute(k_gemm_bias, cudaFuncAttributeMaxDynamicSharedMemorySize, SMEM_BYTES);
    cudaFuncSetAttribute(k_edge1,     cudaFuncAttributeMaxDynamicSharedMemorySize, SMEM_BYTES);
    cudaFuncSetAttribute(k_edge2,     cudaFuncAttributeMaxDynamicSharedMemorySize, SMEM_BYTES);
    cudaFuncSetAttribute(k_node1,     cudaFuncAttributeMaxDynamicSharedMemorySize, SMEM_BYTES);
    cudaFuncSetAttribute(k_node2,     cudaFuncAttributeMaxDynamicSharedMemorySize, SMEM_BYTES);

    float *p_xw1m, *p_xw1n, *p_h1, *p_hn;
    cudaGetSymbolAddress((void**)&p_xw1m, g_xw1m);
    cudaGetSymbolAddress((void**)&p_xw1n, g_xw1n);
    cudaGetSymbolAddress((void**)&p_h1,   g_h1);
    cudaGetSymbolAddress((void**)&p_hn,   g_hn);

    const int nodeBlocks = (NN + TR - 1) / TR;   // 391
    const int edgeBlocks = NE / TR;              // 6250

    k_zero<<<(NN * 64 + NT - 1) / NT, NT>>>();
    k_gemm_bias<<<nodeBlocks, NT, SMEM_BYTES>>>(x, NN, w1m, b1m, p_xw1m);
    k_gemm_bias<<<nodeBlocks, NT, SMEM_BYTES>>>(x, NN, w1n, b1n, p_xw1n);
    k_count<<<(NE + NT - 1) / NT, NT>>>(ei);
    k_inv<<<(NN + NT - 1) / NT, NT>>>();
    k_edge1<<<edgeBlocks, NT, SMEM_BYTES>>>(ea, ei, w1m + 64 * 64);
    k_stats<<<1024, NT>>>(p_h1, NE, 0);
    k_coef<<<1, 64>>>(0, 1.0f / (float)NE, gm, bm);
    k_edge2<<<edgeBlocks, NT, SMEM_BYTES>>>(ei, w2m, b2m);
    k_node1<<<nodeBlocks, NT, SMEM_BYTES>>>(w1n + 64 * 64);
    k_stats<<<256, NT>>>(p_hn, NN, 128);
    k_coef<<<1, 64>>>(128, 1.0f / (float)NN, gn, bn);
    k_node2<<<nodeBlocks, NT, SMEM_BYTES>>>(w2n, b2n, out);
}

// round 3
// speedup vs baseline: 1.3048x; 1.3048x over previous
#include <cuda_runtime.h>
#include <cstdint>

#define NN 50000
#define NE 800000
#define EPSB 1e-5f

#define TR 128            // rows per tile
#define SA2 130           // A_s row stride (even -> 8B-aligned row pairs for LDS.64)
#define NT 256            // threads per block
#define SMEM_FLOATS (64*SA2 + 64*64)     // A_s + W_s
#define SMEM_BYTES  (SMEM_FLOATS * 4)    // 49664 B

// ---------------- scratch (device globals; no allocs allowed) ----------------
__device__ __align__(16) float g_xw1m[NN * 64];     // x @ w1m[:64] + b1m
__device__ __align__(16) float g_xw1n[NN * 64];     // x @ w1n[:64] + b1n
__device__ __align__(16) float g_h1[51200000];      // edge pre-BN activations [E,64]
__device__ __align__(16) float g_hn[NN * 64];       // node pre-BN activations
__device__ __align__(16) float g_agg[NN * 64];      // scatter sums
__device__ float g_inv[NN];
__device__ int   g_cnt[NN];
__device__ float g_stats[256];   // [0:64) sumM [64:128) ssM [128:192) sumN [192:256) ssN
__device__ float g_coef[256];    // [0:64) scaleM [64:128) shiftM [128..] scaleN shiftN

// ---------------- helpers ----------------
__device__ __forceinline__ void red_add4(float* p, float x, float y, float z, float w) {
    asm volatile("red.global.add.v4.f32 [%0], {%1,%2,%3,%4};"
                 :: "l"(p), "f"(x), "f"(y), "f"(z), "f"(w) : "memory");
}

__device__ __forceinline__ void load_W(const float* __restrict__ W, float* W_s, int tid) {
    const float4* wg = reinterpret_cast<const float4*>(W);
    float4* ws = reinterpret_cast<float4*>(W_s);
#pragma unroll
    for (int j = 0; j < 4; ++j) ws[tid + j * NT] = wg[tid + j * NT];
}

__device__ __forceinline__ float2 unpack2(unsigned long long v) {
    float2 r;
    asm("mov.b64 {%0,%1}, %2;" : "=f"(r.x), "=f"(r.y) : "l"(v));
    return r;
}

// packed-f32x2 GEMM core: rows rg*8..rg*8+7 (as 4 row-pairs), cols c4*4..+3
__device__ __forceinline__ void mm64x2(const float* __restrict__ A_s,
                                       const float* __restrict__ W_s,
                                       int rg, int c4, unsigned long long acc[4][4]) {
#pragma unroll 8
    for (int k = 0; k < 64; ++k) {
        const float4 b = *reinterpret_cast<const float4*>(W_s + k * 64 + c4 * 4);
        unsigned long long bd0, bd1, bd2, bd3;
        asm("mov.b64 %0,{%1,%1};" : "=l"(bd0) : "f"(b.x));
        asm("mov.b64 %0,{%1,%1};" : "=l"(bd1) : "f"(b.y));
        asm("mov.b64 %0,{%1,%1};" : "=l"(bd2) : "f"(b.z));
        asm("mov.b64 %0,{%1,%1};" : "=l"(bd3) : "f"(b.w));
        const unsigned long long* ap =
            reinterpret_cast<const unsigned long long*>(A_s + k * SA2 + rg * 8);
#pragma unroll
        for (int i = 0; i < 4; ++i) {
            unsigned long long a = ap[i];
            asm("fma.rn.f32x2 %0, %1, %2, %0;" : "+l"(acc[i][0]) : "l"(a), "l"(bd0));
            asm("fma.rn.f32x2 %0, %1, %2, %0;" : "+l"(acc[i][1]) : "l"(a), "l"(bd1));
            asm("fma.rn.f32x2 %0, %1, %2, %0;" : "+l"(acc[i][2]) : "l"(a), "l"(bd2));
            asm("fma.rn.f32x2 %0, %1, %2, %0;" : "+l"(acc[i][3]) : "l"(a), "l"(bd3));
        }
    }
}

#define ZERO_ACC2(acc) do { \
    _Pragma("unroll") for (int _i = 0; _i < 4; ++_i) { \
        acc[_i][0]=0ull; acc[_i][1]=0ull; acc[_i][2]=0ull; acc[_i][3]=0ull; } } while (0)

// shared-mem column-stat reduction: each thread contributes s[4], q[4] for cols c4*4..+3
__device__ __forceinline__ void stat_reduce(float* buf, int tid, int rg, int c4,
                                            const float s[4], const float q[4], int off) {
    __syncthreads();   // mm reads of A_s/W_s done in all warps before reuse
#pragma unroll
    for (int j = 0; j < 4; ++j) {
        buf[rg * 64 + c4 * 4 + j]        = s[j];
        buf[1024 + rg * 64 + c4 * 4 + j] = q[j];
    }
    __syncthreads();
    if (tid < 128) {
        int c = tid & 63, which = tid >> 6;
        float a = 0.f;
#pragma unroll
        for (int g = 0; g < 16; ++g) a += buf[which * 1024 + g * 64 + c];
        atomicAdd(&g_stats[off + which * 64 + c], a);
    }
}

// ---------------- small kernels ----------------
__global__ void k_zero() {
    int i = blockIdx.x * blockDim.x + threadIdx.x;
    if (i < NN * 64) g_agg[i] = 0.f;
    if (i < NN)      g_cnt[i] = 0;
    if (i < 256)     g_stats[i] = 0.f;
}
__global__ void k_count(const int* __restrict__ ei) {
    int i = blockIdx.x * blockDim.x + threadIdx.x;
    if (i < NE) atomicAdd(&g_cnt[ei[NE + i]], 1);
}
__global__ void k_inv() {
    int i = blockIdx.x * blockDim.x + threadIdx.x;
    if (i < NN) g_inv[i] = 1.0f / fmaxf((float)g_cnt[i], 1.0f);
}
__global__ void k_coef(int off, float invR,
                       const float* __restrict__ gamma, const float* __restrict__ beta) {
    int c = threadIdx.x;  // 64 threads
    float mean = g_stats[off + c] * invR;
    float ms   = g_stats[off + 64 + c] * invR;
    float var  = ms - mean * mean;
    float sc   = gamma[c] * rsqrtf(var + EPSB);
    g_coef[off + c]      = sc;
    g_coef[off + 64 + c] = beta[c] - mean * sc;
}

// ---------------- GEMM kernels (f32x2) ----------------
// out[r] = A[r] @ W + bias  (generic, guarded)
__global__ void k_gemm_bias(const float* __restrict__ A, int R,
                            const float* __restrict__ W,
                            const float* __restrict__ bias,
                            float* __restrict__ out) {
    extern __shared__ float smem[];
    float* A_s = smem;
    float* W_s = smem + 64 * SA2;
    const int tid = threadIdx.x;
    const int base = blockIdx.x * TR;
    load_W(W, W_s, tid);
#pragma unroll
    for (int j = 0; j < 32; ++j) {
        int idx = tid + j * NT;
        int k = idx & 63, row = idx >> 6;
        int r = base + row; if (r > R - 1) r = R - 1;
        A_s[k * SA2 + row] = A[r * 64 + k];
    }
    __syncthreads();
    const int c4 = tid & 15, rg = tid >> 4;
    unsigned long long acc[4][4];
    ZERO_ACC2(acc);
    mm64x2(A_s, W_s, rg, c4, acc);
    const float4 bb = *reinterpret_cast<const float4*>(bias + c4 * 4);
#pragma unroll
    for (int i = 0; i < 4; ++i) {
        float2 p0 = unpack2(acc[i][0]), p1 = unpack2(acc[i][1]);
        float2 p2 = unpack2(acc[i][2]), p3 = unpack2(acc[i][3]);
        int r0 = base + rg * 8 + 2 * i;
        if (r0 < R)
            *reinterpret_cast<float4*>(out + r0 * 64 + c4 * 4) =
                make_float4(p0.x + bb.x, p1.x + bb.y, p2.x + bb.z, p3.x + bb.w);
        if (r0 + 1 < R)
            *reinterpret_cast<float4*>(out + (r0 + 1) * 64 + c4 * 4) =
                make_float4(p0.y + bb.x, p1.y + bb.y, p2.y + bb.z, p3.y + bb.w);
    }
}

// h1[e] = ea[e] @ Wbot + xw1m[send[e]]   + fused BN stats (E % TR == 0)
__global__ void k_edge1(const float* __restrict__ ea,
                        const int* __restrict__ ei,
                        const float* __restrict__ Wbot) {
    extern __shared__ float smem[];
    float* A_s = smem;
    float* W_s = smem + 64 * SA2;
    const int tid = threadIdx.x;
    const int base = blockIdx.x * TR;
    load_W(Wbot, W_s, tid);
#pragma unroll
    for (int j = 0; j < 32; ++j) {
        int idx = tid + j * NT;
        int k = idx & 63, row = idx >> 6;
        A_s[k * SA2 + row] = ea[(long long)(base + row) * 64 + k];
    }
    __syncthreads();
    const int c4 = tid & 15, rg = tid >> 4;
    unsigned long long acc[4][4];
    ZERO_ACC2(acc);
    mm64x2(A_s, W_s, rg, c4, acc);

    float s[4] = {0.f, 0.f, 0.f, 0.f}, q[4] = {0.f, 0.f, 0.f, 0.f};
#pragma unroll
    for (int i = 0; i < 4; ++i) {
        float2 p0 = unpack2(acc[i][0]), p1 = unpack2(acc[i][1]);
        float2 p2 = unpack2(acc[i][2]), p3 = unpack2(acc[i][3]);
        int r0 = base + rg * 8 + 2 * i;
        int s0 = ei[r0], s1 = ei[r0 + 1];
        float4 x0 = *reinterpret_cast<const float4*>(g_xw1m + (long long)s0 * 64 + c4 * 4);
        float4 x1 = *reinterpret_cast<const float4*>(g_xw1m + (long long)s1 * 64 + c4 * 4);
        float4 v0 = make_float4(p0.x + x0.x, p1.x + x0.y, p2.x + x0.z, p3.x + x0.w);
        float4 v1 = make_float4(p0.y + x1.x, p1.y + x1.y, p2.y + x1.z, p3.y + x1.w);
        *reinterpret_cast<float4*>(g_h1 + (long long)r0 * 64 + c4 * 4) = v0;
        *reinterpret_cast<float4*>(g_h1 + (long long)(r0 + 1) * 64 + c4 * 4) = v1;
        s[0] += v0.x + v1.x; q[0] += v0.x * v0.x + v1.x * v1.x;
        s[1] += v0.y + v1.y; q[1] += v0.y * v0.y + v1.y * v1.y;
        s[2] += v0.z + v1.z; q[2] += v0.z * v0.z + v1.z * v1.z;
        s[3] += v0.w + v1.w; q[3] += v0.w * v0.w + v1.w * v1.w;
    }
    stat_reduce(A_s, tid, rg, c4, s, q, 0);
}

// m = relu(h1*scale+shift) @ w2m + b2m ; scatter-add into g_agg[rec]
__global__ void k_edge2(const int* __restrict__ ei,
                        const float* __restrict__ W2,
                        const float* __restrict__ b2) {
    extern __shared__ float smem[];
    float* A_s = smem;
    float* W_s = smem + 64 * SA2;
    const int tid = threadIdx.x;
    const int base = blockIdx.x * TR;
    load_W(W2, W_s, tid);
    const float cs = g_coef[tid & 63];
    const float ch = g_coef[64 + (tid & 63)];
#pragma unroll
    for (int j = 0; j < 32; ++j) {
        int idx = tid + j * NT;
        int k = idx & 63, row = idx >> 6;
        float v = fmaf(g_h1[(long long)(base + row) * 64 + k], cs, ch);
        A_s[k * SA2 + row] = fmaxf(v, 0.f);
    }
    __syncthreads();
    const int c4 = tid & 15, rg = tid >> 4;
    unsigned long long acc[4][4];
    ZERO_ACC2(acc);
    mm64x2(A_s, W_s, rg, c4, acc);
    const float4 bb = *reinterpret_cast<const float4*>(b2 + c4 * 4);
#pragma unroll
    for (int i = 0; i < 4; ++i) {
        float2 p0 = unpack2(acc[i][0]), p1 = unpack2(acc[i][1]);
        float2 p2 = unpack2(acc[i][2]), p3 = unpack2(acc[i][3]);
        int r0 = base + rg * 8 + 2 * i;
        int rec0 = ei[NE + r0], rec1 = ei[NE + r0 + 1];
        red_add4(g_agg + (long long)rec0 * 64 + c4 * 4,
                 p0.x + bb.x, p1.x + bb.y, p2.x + bb.z, p3.x + bb.w);
        red_add4(g_agg + (long long)rec1 * 64 + c4 * 4,
                 p0.y + bb.x, p1.y + bb.y, p2.y + bb.z, p3.y + bb.w);
    }
}

// hn[i] = (agg[i]*inv[i]) @ w1n[64:] + xw1n[i]   + fused BN stats
__global__ void k_node1(const float* __restrict__ Wbot) {
    extern __shared__ float smem[];
    float* A_s = smem;
    float* W_s = smem + 64 * SA2;
    const int tid = threadIdx.x;
    const int base = blockIdx.x * TR;
    load_W(Wbot, W_s, tid);
#pragma unroll
    for (int j = 0; j < 32; ++j) {
        int idx = tid + j * NT;
        int k = idx & 63, row = idx >> 6;
        int r = base + row; if (r > NN - 1) r = NN - 1;
        A_s[k * SA2 + row] = g_agg[r * 64 + k] * g_inv[r];
    }
    __syncthreads();
    const int c4 = tid & 15, rg = tid >> 4;
    unsigned long long acc[4][4];
    ZERO_ACC2(acc);
    mm64x2(A_s, W_s, rg, c4, acc);

    float s[4] = {0.f, 0.f, 0.f, 0.f}, q[4] = {0.f, 0.f, 0.f, 0.f};
#pragma unroll
    for (int i = 0; i < 4; ++i) {
        float2 p0 = unpack2(acc[i][0]), p1 = unpack2(acc[i][1]);
        float2 p2 = unpack2(acc[i][2]), p3 = unpack2(acc[i][3]);
        int r0 = base + rg * 8 + 2 * i;
        if (r0 < NN) {
            float4 xw = *reinterpret_cast<const float4*>(g_xw1n + r0 * 64 + c4 * 4);
            float4 v = make_float4(p0.x + xw.x, p1.x + xw.y, p2.x + xw.z, p3.x + xw.w);
            *reinterpret_cast<float4*>(g_hn + r0 * 64 + c4 * 4) = v;
            s[0] += v.x; q[0] += v.x * v.x;
            s[1] += v.y; q[1] += v.y * v.y;
            s[2] += v.z; q[2] += v.z * v.z;
            s[3] += v.w; q[3] += v.w * v.w;
        }
        if (r0 + 1 < NN) {
            float4 xw = *reinterpret_cast<const float4*>(g_xw1n + (r0 + 1) * 64 + c4 * 4);
            float4 v = make_float4(p0.y + xw.x, p1.y + xw.y, p2.y + xw.z, p3.y + xw.w);
            *reinterpret_cast<float4*>(g_hn + (r0 + 1) * 64 + c4 * 4) = v;
            s[0] += v.x; q[0] += v.x * v.x;
            s[1] += v.y; q[1] += v.y * v.y;
            s[2] += v.z; q[2] += v.z * v.z;
            s[3] += v.w; q[3] += v.w * v.w;
        }
    }
    stat_reduce(A_s, tid, rg, c4, s, q, 128);
}

// out = relu(hn*scaleN+shiftN) @ w2n + b2n
__global__ void k_node2(const float* __restrict__ W2,
                        const float* __restrict__ b2,
                        float* __restrict__ out) {
    extern __shared__ float smem[];
    float* A_s = smem;
    float* W_s = smem + 64 * SA2;
    const int tid = threadIdx.x;
    const int base = blockIdx.x * TR;
    load_W(W2, W_s, tid);
    const float cs = g_coef[128 + (tid & 63)];
    const float ch = g_coef[192 + (tid & 63)];
#pragma unroll
    for (int j = 0; j < 32; ++j) {
        int idx = tid + j * NT;
        int k = idx & 63, row = idx >> 6;
        int r = base + row; if (r > NN - 1) r = NN - 1;
        float v = fmaf(g_hn[r * 64 + k], cs, ch);
        A_s[k * SA2 + row] = fmaxf(v, 0.f);
    }
    __syncthreads();
    const int c4 = tid & 15, rg = tid >> 4;
    unsigned long long acc[4][4];
    ZERO_ACC2(acc);
    mm64x2(A_s, W_s, rg, c4, acc);
    const float4 bb = *reinterpret_cast<const float4*>(b2 + c4 * 4);
#pragma unroll
    for (int i = 0; i < 4; ++i) {
        float2 p0 = unpack2(acc[i][0]), p1 = unpack2(acc[i][1]);
        float2 p2 = unpack2(acc[i][2]), p3 = unpack2(acc[i][3]);
        int r0 = base + rg * 8 + 2 * i;
        if (r0 < NN)
            *reinterpret_cast<float4*>(out + r0 * 64 + c4 * 4) =
                make_float4(p0.x + bb.x, p1.x + bb.y, p2.x + bb.z, p3.x + bb.w);
        if (r0 + 1 < NN)
            *reinterpret_cast<float4*>(out + (r0 + 1) * 64 + c4 * 4) =
                make_float4(p0.y + bb.x, p1.y + bb.y, p2.y + bb.z, p3.y + bb.w);
    }
}

// ---------------- launch ----------------
extern "C" void kernel_launch(void* const* d_in, const int* in_sizes, int n_in,
                              void* d_out, int out_size) {
    const float* x   = (const float*)d_in[0];
    const int*   ei  = (const int*)d_in[1];
    const float* ea  = (const float*)d_in[2];
    const float* w1m = (const float*)d_in[5];
    const float* b1m = (const float*)d_in[6];
    const float* gm  = (const float*)d_in[7];
    const float* bm  = (const float*)d_in[8];
    const float* w2m = (const float*)d_in[9];
    const float* b2m = (const float*)d_in[10];
    const float* w1n = (const float*)d_in[11];
    const float* b1n = (const float*)d_in[12];
    const float* gn  = (const float*)d_in[13];
    const float* bn  = (const float*)d_in[14];
    const float* w2n = (const float*)d_in[15];
    const float* b2n = (const float*)d_in[16];
    float* out = (float*)d_out;

    cudaFuncSetAttribute(k_gemm_bias, cudaFuncAttributeMaxDynamicSharedMemorySize, SMEM_BYTES);
    cudaFuncSetAttribute(k_edge1,     cudaFuncAttributeMaxDynamicSharedMemorySize, SMEM_BYTES);
    cudaFuncSetAttribute(k_edge2,     cudaFuncAttributeMaxDynamicSharedMemorySize, SMEM_BYTES);
    cudaFuncSetAttribute(k_node1,     cudaFuncAttributeMaxDynamicSharedMemorySize, SMEM_BYTES);
    cudaFuncSetAttribute(k_node2,     cudaFuncAttributeMaxDynamicSharedMemorySize, SMEM_BYTES);

    float *p_xw1m, *p_xw1n;
    cudaGetSymbolAddress((void**)&p_xw1m, g_xw1m);
    cudaGetSymbolAddress((void**)&p_xw1n, g_xw1n);

    const int nodeBlocks = (NN + TR - 1) / TR;   // 391
    const int edgeBlocks = NE / TR;              // 6250

    k_zero<<<(NN * 64 + NT - 1) / NT, NT>>>();
    k_gemm_bias<<<nodeBlocks, NT, SMEM_BYTES>>>(x, NN, w1m, b1m, p_xw1m);
    k_gemm_bias<<<nodeBlocks, NT, SMEM_BYTES>>>(x, NN, w1n, b1n, p_xw1n);
    k_count<<<(NE + NT - 1) / NT, NT>>>(ei);
    k_inv<<<(NN + NT - 1) / NT, NT>>>();
    k_edge1<<<edgeBlocks, NT, SMEM_BYTES>>>(ea, ei, w1m + 64 * 64);
    k_coef<<<1, 64>>>(0, 1.0f / (float)NE, gm, bm);
    k_edge2<<<edgeBlocks, NT, SMEM_BYTES>>>(ei, w2m, b2m);
    k_node1<<<nodeBlocks, NT, SMEM_BYTES>>>(w1n + 64 * 64);
    k_coef<<<1, 64>>>(128, 1.0f / (float)NN, gn, bn);
    k_node2<<<nodeBlocks, NT, SMEM_BYTES>>>(w2n, b2n, out);
}

// round 6
// speedup vs baseline: 1.4091x; 1.0799x over previous
#include <cuda_runtime.h>
#include <cuda_bf16.h>
#include <cstdint>

#define NN 50000
#define NE 800000
#define EPSB 1e-5f

#define TR 128            // rows per tile
#define SA2 130           // fp32x2 node kernels: A_s stride
#define NT 256
#define SMEM_FLOATS (64*SA2 + 64*64)
#define SMEM_BYTES  (SMEM_FLOATS * 4)

// ---- mma edge kernel smem (bytes) ----
#define SAB 72                       // bf16 row stride (pad: conflict-free frags)
#define AHI_B 0
#define ALO_B 18432                  // 128*72*2
#define BHI_B 36864
#define BLO_B 46080                  // + 64*72*2
#define SBUF_B 55296                 // 512 floats stat slots
#define EDGE_SMEM 57344

// ---------------- scratch ----------------
__device__ __align__(16) float g_xw1m[NN * 64];
__device__ __align__(16) float g_xw1n[NN * 64];
__device__ __align__(16) float g_h1[51200000];
__device__ __align__(16) float g_hn[NN * 64];
__device__ __align__(16) float g_agg[NN * 64];
__device__ float g_inv[NN];
__device__ int   g_cnt[NN];
__device__ float g_stats[256];
__device__ float g_coef[256];

// ---------------- helpers ----------------
__device__ __forceinline__ void red_add2(float* p, float x, float y) {
    asm volatile("red.global.add.v2.f32 [%0], {%1,%2};" :: "l"(p), "f"(x), "f"(y) : "memory");
}
#define MMA16816(d, a, b) \
    asm volatile("mma.sync.aligned.m16n8k16.row.col.f32.bf16.bf16.f32 " \
        "{%0,%1,%2,%3}, {%4,%5,%6,%7}, {%8,%9}, {%0,%1,%2,%3};" \
        : "+f"((d)[0]), "+f"((d)[1]), "+f"((d)[2]), "+f"((d)[3]) \
        : "r"((a)[0]), "r"((a)[1]), "r"((a)[2]), "r"((a)[3]), "r"((b)[0]), "r"((b)[1]))

__device__ __forceinline__ uint32_t ld32bf(const __nv_bfloat16* p) {
    return *reinterpret_cast<const uint32_t*>(p);
}
__device__ __forceinline__ void split_store(float4 v, char* hiP, char* loP) {
    __nv_bfloat162 h01 = __float22bfloat162_rn(make_float2(v.x, v.y));
    __nv_bfloat162 h23 = __float22bfloat162_rn(make_float2(v.z, v.w));
    float2 f01 = __bfloat1622float2(h01);
    float2 f23 = __bfloat1622float2(h23);
    __nv_bfloat162 l01 = __float22bfloat162_rn(make_float2(v.x - f01.x, v.y - f01.y));
    __nv_bfloat162 l23 = __float22bfloat162_rn(make_float2(v.z - f23.x, v.w - f23.y));
    *reinterpret_cast<uint2*>(hiP) = make_uint2(*reinterpret_cast<uint32_t*>(&h01),
                                                *reinterpret_cast<uint32_t*>(&h23));
    *reinterpret_cast<uint2*>(loP) = make_uint2(*reinterpret_cast<uint32_t*>(&l01),
                                                *reinterpret_cast<uint32_t*>(&l23));
}

// ---------------- tensor-core edge kernels ----------------
// MODE 0: h1 = ea @ Wbot + xw1m[send]  + fused stats + receiver counts
// MODE 1: relu(BN(h1)) @ W2 + b2 -> red.add g_agg[rec]
template<int MODE>
__global__ void __launch_bounds__(256) k_edge_mma(
    const float* __restrict__ inA,
    float*       __restrict__ h1out,
    const int*   __restrict__ ei,
    const float* __restrict__ W,
    const float* __restrict__ b2)
{
    extern __shared__ char smem[];
    __nv_bfloat16* Ahi = (__nv_bfloat16*)(smem + AHI_B);
    __nv_bfloat16* Alo = (__nv_bfloat16*)(smem + ALO_B);
    __nv_bfloat16* Bhi = (__nv_bfloat16*)(smem + BHI_B);
    __nv_bfloat16* Blo = (__nv_bfloat16*)(smem + BLO_B);
    float* sbuf = (float*)(smem + SBUF_B);

    const int tid = threadIdx.x;
    const int base = blockIdx.x * TR;

    // ---- B (weights) -> bf16 hi/lo planes, [n][k] layout ----
#pragma unroll 4
    for (int it = 0; it < 16; ++it) {
        int idx = tid + it * 256;
        int k = idx >> 6, n = idx & 63;
        float w = __ldg(W + k * 64 + n);
        __nv_bfloat16 hi = __float2bfloat16(w);
        __nv_bfloat16 lo = __float2bfloat16(w - __bfloat162float(hi));
        Bhi[n * SAB + k] = hi;
        Blo[n * SAB + k] = lo;
    }

    // ---- A tile [128,64] fp32 -> bf16 hi/lo (BN+relu for MODE 1) ----
    const float4* src4 = reinterpret_cast<const float4*>(inA);
#pragma unroll 4
    for (int it = 0; it < 8; ++it) {
        int chunk = tid + it * 256;
        int row = chunk >> 4, c4 = chunk & 15;
        float4 v = __ldg(src4 + (long long)(base + row) * 16 + c4);
        if (MODE == 1) {
            float4 cs = *reinterpret_cast<const float4*>(g_coef + c4 * 4);
            float4 ch = *reinterpret_cast<const float4*>(g_coef + 64 + c4 * 4);
            v.x = fmaxf(fmaf(v.x, cs.x, ch.x), 0.f);
            v.y = fmaxf(fmaf(v.y, cs.y, ch.y), 0.f);
            v.z = fmaxf(fmaf(v.z, cs.z, ch.z), 0.f);
            v.w = fmaxf(fmaf(v.w, cs.w, ch.w), 0.f);
        }
        int o = row * SAB + c4 * 4;
        split_store(v, (char*)(Ahi + o), (char*)(Alo + o));
    }
    __syncthreads();

    // ---- warp tiling: warp w -> rows (w>>1)*32..+31, cols (w&1)*32..+31 ----
    const int w = tid >> 5, l = tid & 31;
    const int g = l >> 2, tg = l & 3;
    const int mrow = (w >> 1) * 32, ncol = (w & 1) * 32;

    float d[2][4][4];
#pragma unroll
    for (int mt = 0; mt < 2; ++mt)
#pragma unroll
        for (int nt = 0; nt < 4; ++nt)
#pragma unroll
            for (int j = 0; j < 4; ++j) d[mt][nt][j] = 0.f;

#pragma unroll
    for (int kit = 0; kit < 4; ++kit) {
        const int kb = kit * 16 + 2 * tg;
        uint32_t ahi[2][4], alo[2][4], bhi[4][2], blo[4][2];
#pragma unroll
        for (int mt = 0; mt < 2; ++mt) {
            const int r = mrow + mt * 16 + g;
            ahi[mt][0] = ld32bf(Ahi + r * SAB + kb);
            ahi[mt][1] = ld32bf(Ahi + (r + 8) * SAB + kb);
            ahi[mt][2] = ld32bf(Ahi + r * SAB + kb + 8);
            ahi[mt][3] = ld32bf(Ahi + (r + 8) * SAB + kb + 8);
            alo[mt][0] = ld32bf(Alo + r * SAB + kb);
            alo[mt][1] = ld32bf(Alo + (r + 8) * SAB + kb);
            alo[mt][2] = ld32bf(Alo + r * SAB + kb + 8);
            alo[mt][3] = ld32bf(Alo + (r + 8) * SAB + kb + 8);
        }
#pragma unroll
        for (int nt = 0; nt < 4; ++nt) {
            const int n = ncol + nt * 8 + g;
            bhi[nt][0] = ld32bf(Bhi + n * SAB + kb);
            bhi[nt][1] = ld32bf(Bhi + n * SAB + kb + 8);
            blo[nt][0] = ld32bf(Blo + n * SAB + kb);
            blo[nt][1] = ld32bf(Blo + n * SAB + kb + 8);
        }
#pragma unroll
        for (int mt = 0; mt < 2; ++mt)
#pragma unroll
            for (int nt = 0; nt < 4; ++nt) {
                MMA16816(d[mt][nt], ahi[mt], bhi[nt]);
                MMA16816(d[mt][nt], ahi[mt], blo[nt]);
                MMA16816(d[mt][nt], alo[mt], bhi[nt]);
            }
    }

    // ---- epilogue ----
    float s8[8], q8[8];
#pragma unroll
    for (int j = 0; j < 8; ++j) { s8[j] = 0.f; q8[j] = 0.f; }

#pragma unroll
    for (int mt = 0; mt < 2; ++mt) {
#pragma unroll
        for (int h = 0; h < 2; ++h) {
            const int rl = mrow + mt * 16 + g + h * 8;
            const long long rr = base + rl;
            if (MODE == 0) {
                const int snd = __ldg(ei + rr);
                if (tg == 0 && (w & 1) == 0)
                    atomicAdd(&g_cnt[__ldg(ei + NE + rr)], 1);
                const float2* xw = reinterpret_cast<const float2*>(g_xw1m + (long long)snd * 64);
#pragma unroll
                for (int nt = 0; nt < 4; ++nt) {
                    const int c = ncol + nt * 8 + 2 * tg;
                    float2 xv = __ldg(xw + (c >> 1));
                    float vx = d[mt][nt][h * 2 + 0] + xv.x;
                    float vy = d[mt][nt][h * 2 + 1] + xv.y;
                    *reinterpret_cast<float2*>(h1out + rr * 64 + c) = make_float2(vx, vy);
                    s8[nt * 2 + 0] += vx; q8[nt * 2 + 0] += vx * vx;
                    s8[nt * 2 + 1] += vy; q8[nt * 2 + 1] += vy * vy;
                }
            } else {
                const int rec = __ldg(ei + NE + rr);
                float* dst = g_agg + (long long)rec * 64;
#pragma unroll
                for (int nt = 0; nt < 4; ++nt) {
                    const int c = ncol + nt * 8 + 2 * tg;
                    float2 bb = __ldg(reinterpret_cast<const float2*>(b2 + c));
                    red_add2(dst + c, d[mt][nt][h * 2 + 0] + bb.x,
                                      d[mt][nt][h * 2 + 1] + bb.y);
                }
            }
        }
    }

    if (MODE == 0) {
        // reduce stats across the 8 g-lanes (same tg -> same columns)
#pragma unroll
        for (int off = 4; off < 32; off <<= 1) {
#pragma unroll
            for (int j = 0; j < 8; ++j) {
                s8[j] += __shfl_xor_sync(0xFFFFFFFFu, s8[j], off);
                q8[j] += __shfl_xor_sync(0xFFFFFFFFu, q8[j], off);
            }
        }
        if (g == 0) {
            const int slot = w >> 1;   // warps sharing ncol get distinct slots
#pragma unroll
            for (int nt = 0; nt < 4; ++nt) {
                const int c = ncol + nt * 8 + 2 * tg;
                *reinterpret_cast<float2*>(sbuf + slot * 64 + c) =
                    make_float2(s8[nt * 2], s8[nt * 2 + 1]);
                *reinterpret_cast<float2*>(sbuf + (4 + slot) * 64 + c) =
                    make_float2(q8[nt * 2], q8[nt * 2 + 1]);
            }
        }
        __syncthreads();
        if (tid < 128) {
            const int stat = tid >> 6, c = tid & 63;
            float a = sbuf[(stat * 4 + 0) * 64 + c] + sbuf[(stat * 4 + 1) * 64 + c]
                    + sbuf[(stat * 4 + 2) * 64 + c] + sbuf[(stat * 4 + 3) * 64 + c];
            atomicAdd(&g_stats[stat * 64 + c], a);
        }
    }
}

// ---------------- fp32x2 node-side kernels ----------------
__device__ __forceinline__ void load_W(const float* __restrict__ W, float* W_s, int tid) {
    const float4* wg = reinterpret_cast<const float4*>(W);
    float4* ws = reinterpret_cast<float4*>(W_s);
#pragma unroll
    for (int j = 0; j < 4; ++j) ws[tid + j * NT] = wg[tid + j * NT];
}
__device__ __forceinline__ float2 unpack2(unsigned long long v) {
    float2 r;
    asm("mov.b64 {%0,%1}, %2;" : "=f"(r.x), "=f"(r.y) : "l"(v));
    return r;
}
__device__ __forceinline__ void mm64x2(const float* __restrict__ A_s,
                                       const float* __restrict__ W_s,
                                       int rg, int c4, unsigned long long acc[4][4]) {
#pragma unroll 8
    for (int k = 0; k < 64; ++k) {
        const float4 b = *reinterpret_cast<const float4*>(W_s + k * 64 + c4 * 4);
        unsigned long long bd0, bd1, bd2, bd3;
        asm("mov.b64 %0,{%1,%1};" : "=l"(bd0) : "f"(b.x));
        asm("mov.b64 %0,{%1,%1};" : "=l"(bd1) : "f"(b.y));
        asm("mov.b64 %0,{%1,%1};" : "=l"(bd2) : "f"(b.z));
        asm("mov.b64 %0,{%1,%1};" : "=l"(bd3) : "f"(b.w));
        const unsigned long long* ap =
            reinterpret_cast<const unsigned long long*>(A_s + k * SA2 + rg * 8);
#pragma unroll
        for (int i = 0; i < 4; ++i) {
            unsigned long long a = ap[i];
            asm("fma.rn.f32x2 %0, %1, %2, %0;" : "+l"(acc[i][0]) : "l"(a), "l"(bd0));
            asm("fma.rn.f32x2 %0, %1, %2, %0;" : "+l"(acc[i][1]) : "l"(a), "l"(bd1));
            asm("fma.rn.f32x2 %0, %1, %2, %0;" : "+l"(acc[i][2]) : "l"(a), "l"(bd2));
            asm("fma.rn.f32x2 %0, %1, %2, %0;" : "+l"(acc[i][3]) : "l"(a), "l"(bd3));
        }
    }
}
#define ZERO_ACC2(acc) do { \
    _Pragma("unroll") for (int _i = 0; _i < 4; ++_i) { \
        acc[_i][0]=0ull; acc[_i][1]=0ull; acc[_i][2]=0ull; acc[_i][3]=0ull; } } while (0)

__device__ __forceinline__ void stat_reduce(float* buf, int tid, int rg, int c4,
                                            const float s[4], const float q[4], int off) {
    __syncthreads();
#pragma unroll
    for (int j = 0; j < 4; ++j) {
        buf[rg * 64 + c4 * 4 + j]        = s[j];
        buf[1024 + rg * 64 + c4 * 4 + j] = q[j];
    }
    __syncthreads();
    if (tid < 128) {
        int c = tid & 63, which = tid >> 6;
        float a = 0.f;
#pragma unroll
        for (int gg = 0; gg < 16; ++gg) a += buf[which * 1024 + gg * 64 + c];
        atomicAdd(&g_stats[off + which * 64 + c], a);
    }
}

__global__ void k_zero() {
    int i = blockIdx.x * blockDim.x + threadIdx.x;
    if (i < NN * 64) g_agg[i] = 0.f;
    if (i < NN)      g_cnt[i] = 0;
    if (i < 256)     g_stats[i] = 0.f;
}
__global__ void k_inv() {
    int i = blockIdx.x * blockDim.x + threadIdx.x;
    if (i < NN) g_inv[i] = 1.0f / fmaxf((float)g_cnt[i], 1.0f);
}
__global__ void k_coef(int off, float invR,
                       const float* __restrict__ gamma, const float* __restrict__ beta) {
    int c = threadIdx.x;
    float mean = g_stats[off + c] * invR;
    float ms   = g_stats[off + 64 + c] * invR;
    float var  = ms - mean * mean;
    float sc   = gamma[c] * rsqrtf(var + EPSB);
    g_coef[off + c]      = sc;
    g_coef[off + 64 + c] = beta[c] - mean * sc;
}
__global__ void k_gemm_bias(const float* __restrict__ A, int R,
                            const float* __restrict__ W,
                            const float* __restrict__ bias,
                            float* __restrict__ out) {
    extern __shared__ float smemf[];
    float* A_s = smemf;
    float* W_s = smemf + 64 * SA2;
    const int tid = threadIdx.x;
    const int base = blockIdx.x * TR;
    load_W(W, W_s, tid);
#pragma unroll
    for (int j = 0; j < 32; ++j) {
        int idx = tid + j * NT;
        int k = idx & 63, row = idx >> 6;
        int r = base + row; if (r > R - 1) r = R - 1;
        A_s[k * SA2 + row] = A[r * 64 + k];
    }
    __syncthreads();
    const int c4 = tid & 15, rg = tid >> 4;
    unsigned long long acc[4][4];
    ZERO_ACC2(acc);
    mm64x2(A_s, W_s, rg, c4, acc);
    const float4 bb = *reinterpret_cast<const float4*>(bias + c4 * 4);
#pragma unroll
    for (int i = 0; i < 4; ++i) {
        float2 p0 = unpack2(acc[i][0]), p1 = unpack2(acc[i][1]);
        float2 p2 = unpack2(acc[i][2]), p3 = unpack2(acc[i][3]);
        int r0 = base + rg * 8 + 2 * i;
        if (r0 < R)
            *reinterpret_cast<float4*>(out + r0 * 64 + c4 * 4) =
                make_float4(p0.x + bb.x, p1.x + bb.y, p2.x + bb.z, p3.x + bb.w);
        if (r0 + 1 < R)
            *reinterpret_cast<float4*>(out + (r0 + 1) * 64 + c4 * 4) =
                make_float4(p0.y + bb.x, p1.y + bb.y, p2.y + bb.z, p3.y + bb.w);
    }
}
__global__ void k_node1(const float* __restrict__ Wbot) {
    extern __shared__ float smemf[];
    float* A_s = smemf;
    float* W_s = smemf + 64 * SA2;
    const int tid = threadIdx.x;
    const int base = blockIdx.x * TR;
    load_W(Wbot, W_s, tid);
#pragma unroll
    for (int j = 0; j < 32; ++j) {
        int idx = tid + j * NT;
        int k = idx & 63, row = idx >> 6;
        int r = base + row; if (r > NN - 1) r = NN - 1;
        A_s[k * SA2 + row] = g_agg[r * 64 + k] * g_inv[r];
    }
    __syncthreads();
    const int c4 = tid & 15, rg = tid >> 4;
    unsigned long long acc[4][4];
    ZERO_ACC2(acc);
    mm64x2(A_s, W_s, rg, c4, acc);
    float s[4] = {0.f,0.f,0.f,0.f}, q[4] = {0.f,0.f,0.f,0.f};
#pragma unroll
    for (int i = 0; i < 4; ++i) {
        float2 p0 = unpack2(acc[i][0]), p1 = unpack2(acc[i][1]);
        float2 p2 = unpack2(acc[i][2]), p3 = unpack2(acc[i][3]);
        int r0 = base + rg * 8 + 2 * i;
        if (r0 < NN) {
            float4 xw = *reinterpret_cast<const float4*>(g_xw1n + r0 * 64 + c4 * 4);
            float4 v = make_float4(p0.x + xw.x, p1.x + xw.y, p2.x + xw.z, p3.x + xw.w);
            *reinterpret_cast<float4*>(g_hn + r0 * 64 + c4 * 4) = v;
            s[0] += v.x; q[0] += v.x * v.x; s[1] += v.y; q[1] += v.y * v.y;
            s[2] += v.z; q[2] += v.z * v.z; s[3] += v.w; q[3] += v.w * v.w;
        }
        if (r0 + 1 < NN) {
            float4 xw = *reinterpret_cast<const float4*>(g_xw1n + (r0 + 1) * 64 + c4 * 4);
            float4 v = make_float4(p0.y + xw.x, p1.y + xw.y, p2.y + xw.z, p3.y + xw.w);
            *reinterpret_cast<float4*>(g_hn + (r0 + 1) * 64 + c4 * 4) = v;
            s[0] += v.x; q[0] += v.x * v.x; s[1] += v.y; q[1] += v.y * v.y;
            s[2] += v.z; q[2] += v.z * v.z; s[3] += v.w; q[3] += v.w * v.w;
        }
    }
    stat_reduce(A_s, tid, rg, c4, s, q, 128);
}
__global__ void k_node2(const float* __restrict__ W2,
                        const float* __restrict__ b2,
                        float* __restrict__ out) {
    extern __shared__ float smemf[];
    float* A_s = smemf;
    float* W_s = smemf + 64 * SA2;
    const int tid = threadIdx.x;
    const int base = blockIdx.x * TR;
    load_W(W2, W_s, tid);
    const float cs = g_coef[128 + (tid & 63)];
    const float ch = g_coef[192 + (tid & 63)];
#pragma unroll
    for (int j = 0; j < 32; ++j) {
        int idx = tid + j * NT;
        int k = idx & 63, row = idx >> 6;
        int r = base + row; if (r > NN - 1) r = NN - 1;
        float v = fmaf(g_hn[r * 64 + k], cs, ch);
        A_s[k * SA2 + row] = fmaxf(v, 0.f);
    }
    __syncthreads();
    const int c4 = tid & 15, rg = tid >> 4;
    unsigned long long acc[4][4];
    ZERO_ACC2(acc);
    mm64x2(A_s, W_s, rg, c4, acc);
    const float4 bb = *reinterpret_cast<const float4*>(b2 + c4 * 4);
#pragma unroll
    for (int i = 0; i < 4; ++i) {
        float2 p0 = unpack2(acc[i][0]), p1 = unpack2(acc[i][1]);
        float2 p2 = unpack2(acc[i][2]), p3 = unpack2(acc[i][3]);
        int r0 = base + rg * 8 + 2 * i;
        if (r0 < NN)
            *reinterpret_cast<float4*>(out + r0 * 64 + c4 * 4) =
                make_float4(p0.x + bb.x, p1.x + bb.y, p2.x + bb.z, p3.x + bb.w);
        if (r0 + 1 < NN)
            *reinterpret_cast<float4*>(out + (r0 + 1) * 64 + c4 * 4) =
                make_float4(p0.y + bb.x, p1.y + bb.y, p2.y + bb.z, p3.y + bb.w);
    }
}

// ---------------- launch ----------------
extern "C" void kernel_launch(void* const* d_in, const int* in_sizes, int n_in,
                              void* d_out, int out_size) {
    const float* x   = (const float*)d_in[0];
    const int*   ei  = (const int*)d_in[1];
    const float* ea  = (const float*)d_in[2];
    const float* w1m = (const float*)d_in[5];
    const float* b1m = (const float*)d_in[6];
    const float* gm  = (const float*)d_in[7];
    const float* bm  = (const float*)d_in[8];
    const float* w2m = (const float*)d_in[9];
    const float* b2m = (const float*)d_in[10];
    const float* w1n = (const float*)d_in[11];
    const float* b1n = (const float*)d_in[12];
    const float* gn  = (const float*)d_in[13];
    const float* bn  = (const float*)d_in[14];
    const float* w2n = (const float*)d_in[15];
    const float* b2n = (const float*)d_in[16];
    float* out = (float*)d_out;

    cudaFuncSetAttribute(k_gemm_bias, cudaFuncAttributeMaxDynamicSharedMemorySize, SMEM_BYTES);
    cudaFuncSetAttribute(k_node1,     cudaFuncAttributeMaxDynamicSharedMemorySize, SMEM_BYTES);
    cudaFuncSetAttribute(k_node2,     cudaFuncAttributeMaxDynamicSharedMemorySize, SMEM_BYTES);
    cudaFuncSetAttribute(k_edge_mma<0>, cudaFuncAttributeMaxDynamicSharedMemorySize, EDGE_SMEM);
    cudaFuncSetAttribute(k_edge_mma<1>, cudaFuncAttributeMaxDynamicSharedMemorySize, EDGE_SMEM);

    float *p_xw1m, *p_xw1n, *p_h1;
    cudaGetSymbolAddress((void**)&p_xw1m, g_xw1m);
    cudaGetSymbolAddress((void**)&p_xw1n, g_xw1n);
    cudaGetSymbolAddress((void**)&p_h1,   g_h1);

    const int nodeBlocks = (NN + TR - 1) / TR;
    const int edgeBlocks = NE / TR;

    k_zero<<<(NN * 64 + NT - 1) / NT, NT>>>();
    k_gemm_bias<<<nodeBlocks, NT, SMEM_BYTES>>>(x, NN, w1m, b1m, p_xw1m);
    k_gemm_bias<<<nodeBlocks, NT, SMEM_BYTES>>>(x, NN, w1n, b1n, p_xw1n);
    k_edge_mma<0><<<edgeBlocks, 256, EDGE_SMEM>>>(ea, p_h1, ei, w1m + 64 * 64, b1m);
    k_inv<<<(NN + NT - 1) / NT, NT>>>();
    k_coef<<<1, 64>>>(0, 1.0f / (float)NE, gm, bm);
    k_edge_mma<1><<<edgeBlocks, 256, EDGE_SMEM>>>(p_h1, p_h1, ei, w2m, b2m);
    k_node1<<<nodeBlocks, NT, SMEM_BYTES>>>(w1n + 64 * 64);
    k_coef<<<1, 64>>>(128, 1.0f / (float)NN, gn, bn);
    k_node2<<<nodeBlocks, NT, SMEM_BYTES>>>(w2n, b2n, out);
}

// round 7
// speedup vs baseline: 1.6093x; 1.1421x over previous
#include <cuda_runtime.h>
#include <cuda_bf16.h>
#include <cstdint>

#define NN 50000
#define NE 800000
#define EPSB 1e-5f

#define TR 128
#define NTILES (NE / TR)      // 6250
#define EDGE_GRID 296
#define SA2 130               // fp32x2 node kernels: A_s stride
#define NT 256
#define SMEM_FLOATS (64*SA2 + 64*64)
#define SMEM_BYTES  (SMEM_FLOATS * 4)

// ---- edge kernel smem (bytes) ----
#define SAB 72                // bf16 row stride
// edge1: Ahi | Alo | Bhi | Blo | sbuf
#define E1_AHI 0
#define E1_ALO 18432
#define E1_BHI 36864
#define E1_BLO 46080
#define E1_SBUF 55296
#define E1_SMEM 57344
// edge2: A | Bhi | Blo
#define E2_A   0
#define E2_BHI 18432
#define E2_BLO 27648
#define E2_SMEM 36864

// ---------------- scratch ----------------
__device__ __align__(16) float g_xw1m[NN * 64];
__device__ __align__(16) float g_xw1n[NN * 64];
__device__ __align__(16) __nv_bfloat16 g_h1[NE * 64];   // edge activations, bf16
__device__ __align__(16) float g_hn[NN * 64];
__device__ __align__(16) float g_agg[NN * 64];
__device__ float g_inv[NN];
__device__ int   g_cnt[NN];
__device__ float g_stats[256];
__device__ float g_coef[256];

// ---------------- helpers ----------------
__device__ __forceinline__ void red_add2(float* p, float x, float y) {
    asm volatile("red.global.add.v2.f32 [%0], {%1,%2};" :: "l"(p), "f"(x), "f"(y) : "memory");
}
#define MMA16816(d, a, b) \
    asm volatile("mma.sync.aligned.m16n8k16.row.col.f32.bf16.bf16.f32 " \
        "{%0,%1,%2,%3}, {%4,%5,%6,%7}, {%8,%9}, {%0,%1,%2,%3};" \
        : "+f"((d)[0]), "+f"((d)[1]), "+f"((d)[2]), "+f"((d)[3]) \
        : "r"((a)[0]), "r"((a)[1]), "r"((a)[2]), "r"((a)[3]), "r"((b)[0]), "r"((b)[1]))

__device__ __forceinline__ uint32_t ld32bf(const __nv_bfloat16* p) {
    return *reinterpret_cast<const uint32_t*>(p);
}
__device__ __forceinline__ void split_store(float4 v, char* hiP, char* loP) {
    __nv_bfloat162 h01 = __float22bfloat162_rn(make_float2(v.x, v.y));
    __nv_bfloat162 h23 = __float22bfloat162_rn(make_float2(v.z, v.w));
    float2 f01 = __bfloat1622float2(h01);
    float2 f23 = __bfloat1622float2(h23);
    __nv_bfloat162 l01 = __float22bfloat162_rn(make_float2(v.x - f01.x, v.y - f01.y));
    __nv_bfloat162 l23 = __float22bfloat162_rn(make_float2(v.z - f23.x, v.w - f23.y));
    *reinterpret_cast<uint2*>(hiP) = make_uint2(*reinterpret_cast<uint32_t*>(&h01),
                                                *reinterpret_cast<uint32_t*>(&h23));
    *reinterpret_cast<uint2*>(loP) = make_uint2(*reinterpret_cast<uint32_t*>(&l01),
                                                *reinterpret_cast<uint32_t*>(&l23));
}
__device__ __forceinline__ void convert_B(const float* __restrict__ W,
                                          __nv_bfloat16* Bhi, __nv_bfloat16* Blo, int tid) {
#pragma unroll 4
    for (int it = 0; it < 16; ++it) {
        int idx = tid + it * 256;
        int k = idx >> 6, n = idx & 63;
        float w = __ldg(W + k * 64 + n);
        __nv_bfloat16 hi = __float2bfloat16(w);
        __nv_bfloat16 lo = __float2bfloat16(w - __bfloat162float(hi));
        Bhi[n * SAB + k] = hi;
        Blo[n * SAB + k] = lo;
    }
}

// ---------------- edge1: h1 = bf16(ea @ Wbot + xw1m[send]), fused stats + counts ----------------
__global__ void __launch_bounds__(256) k_edge1(
    const float* __restrict__ ea,
    __nv_bfloat16* __restrict__ h1out,
    const int*   __restrict__ ei,
    const float* __restrict__ W)
{
    extern __shared__ char smem[];
    __nv_bfloat16* Ahi = (__nv_bfloat16*)(smem + E1_AHI);
    __nv_bfloat16* Alo = (__nv_bfloat16*)(smem + E1_ALO);
    __nv_bfloat16* Bhi = (__nv_bfloat16*)(smem + E1_BHI);
    __nv_bfloat16* Blo = (__nv_bfloat16*)(smem + E1_BLO);
    float* sbuf = (float*)(smem + E1_SBUF);

    const int tid = threadIdx.x;
    convert_B(W, Bhi, Blo, tid);

    const int w = tid >> 5, l = tid & 31;
    const int g = l >> 2, tg = l & 3;
    const int mrow = (w >> 1) * 32, ncol = (w & 1) * 32;

    float s8[8], q8[8];
#pragma unroll
    for (int j = 0; j < 8; ++j) { s8[j] = 0.f; q8[j] = 0.f; }

    const float4* src4 = reinterpret_cast<const float4*>(ea);

    for (int t = blockIdx.x; t < NTILES; t += EDGE_GRID) {
        const int base = t * TR;
        __syncthreads();   // previous tile's fragment reads done
#pragma unroll 4
        for (int it = 0; it < 8; ++it) {
            int chunk = tid + it * 256;
            int row = chunk >> 4, c4 = chunk & 15;
            float4 v = __ldg(src4 + (long long)(base + row) * 16 + c4);
            int o = row * SAB + c4 * 4;
            split_store(v, (char*)(Ahi + o), (char*)(Alo + o));
        }
        __syncthreads();

        float d[2][4][4];
#pragma unroll
        for (int mt = 0; mt < 2; ++mt)
#pragma unroll
            for (int nt = 0; nt < 4; ++nt)
#pragma unroll
                for (int j = 0; j < 4; ++j) d[mt][nt][j] = 0.f;

#pragma unroll
        for (int kit = 0; kit < 4; ++kit) {
            const int kb = kit * 16 + 2 * tg;
            uint32_t ahi[2][4], alo[2][4], bhi[4][2], blo[4][2];
#pragma unroll
            for (int mt = 0; mt < 2; ++mt) {
                const int r = mrow + mt * 16 + g;
                ahi[mt][0] = ld32bf(Ahi + r * SAB + kb);
                ahi[mt][1] = ld32bf(Ahi + (r + 8) * SAB + kb);
                ahi[mt][2] = ld32bf(Ahi + r * SAB + kb + 8);
                ahi[mt][3] = ld32bf(Ahi + (r + 8) * SAB + kb + 8);
                alo[mt][0] = ld32bf(Alo + r * SAB + kb);
                alo[mt][1] = ld32bf(Alo + (r + 8) * SAB + kb);
                alo[mt][2] = ld32bf(Alo + r * SAB + kb + 8);
                alo[mt][3] = ld32bf(Alo + (r + 8) * SAB + kb + 8);
            }
#pragma unroll
            for (int nt = 0; nt < 4; ++nt) {
                const int n = ncol + nt * 8 + g;
                bhi[nt][0] = ld32bf(Bhi + n * SAB + kb);
                bhi[nt][1] = ld32bf(Bhi + n * SAB + kb + 8);
                blo[nt][0] = ld32bf(Blo + n * SAB + kb);
                blo[nt][1] = ld32bf(Blo + n * SAB + kb + 8);
            }
#pragma unroll
            for (int mt = 0; mt < 2; ++mt)
#pragma unroll
                for (int nt = 0; nt < 4; ++nt) {
                    MMA16816(d[mt][nt], ahi[mt], bhi[nt]);
                    MMA16816(d[mt][nt], ahi[mt], blo[nt]);
                    MMA16816(d[mt][nt], alo[mt], bhi[nt]);
                }
        }

        // epilogue: gather xw1m, add, store bf16, accumulate stats, count receivers
#pragma unroll
        for (int mt = 0; mt < 2; ++mt) {
#pragma unroll
            for (int h = 0; h < 2; ++h) {
                const int rl = mrow + mt * 16 + g + h * 8;
                const long long rr = base + rl;
                const int snd = __ldg(ei + rr);
                if (tg == 0 && (w & 1) == 0)
                    atomicAdd(&g_cnt[__ldg(ei + NE + rr)], 1);
                const float2* xw = reinterpret_cast<const float2*>(g_xw1m + (long long)snd * 64);
#pragma unroll
                for (int nt = 0; nt < 4; ++nt) {
                    const int c = ncol + nt * 8 + 2 * tg;
                    float2 xv = __ldg(xw + (c >> 1));
                    float vx = d[mt][nt][h * 2 + 0] + xv.x;
                    float vy = d[mt][nt][h * 2 + 1] + xv.y;
                    __nv_bfloat162 hv = __float22bfloat162_rn(make_float2(vx, vy));
                    *reinterpret_cast<uint32_t*>(h1out + rr * 64 + c) =
                        *reinterpret_cast<uint32_t*>(&hv);
                    s8[nt * 2 + 0] += vx; q8[nt * 2 + 0] += vx * vx;
                    s8[nt * 2 + 1] += vy; q8[nt * 2 + 1] += vy * vy;
                }
            }
        }
    }

    // final BN-stat reduction (once per CTA)
#pragma unroll
    for (int off = 4; off < 32; off <<= 1) {
#pragma unroll
        for (int j = 0; j < 8; ++j) {
            s8[j] += __shfl_xor_sync(0xFFFFFFFFu, s8[j], off);
            q8[j] += __shfl_xor_sync(0xFFFFFFFFu, q8[j], off);
        }
    }
    __syncthreads();
    if (g == 0) {
        const int slot = w >> 1;
#pragma unroll
        for (int nt = 0; nt < 4; ++nt) {
            const int c = ncol + nt * 8 + 2 * tg;
            *reinterpret_cast<float2*>(sbuf + slot * 64 + c) =
                make_float2(s8[nt * 2], s8[nt * 2 + 1]);
            *reinterpret_cast<float2*>(sbuf + (4 + slot) * 64 + c) =
                make_float2(q8[nt * 2], q8[nt * 2 + 1]);
        }
    }
    __syncthreads();
    if (tid < 128) {
        const int stat = tid >> 6, c = tid & 63;
        float a = sbuf[(stat * 4 + 0) * 64 + c] + sbuf[(stat * 4 + 1) * 64 + c]
                + sbuf[(stat * 4 + 2) * 64 + c] + sbuf[(stat * 4 + 3) * 64 + c];
        atomicAdd(&g_stats[stat * 64 + c], a);
    }
}

// ---------------- edge2: relu(BN(h1)) @ W2 + b2 -> red.add g_agg[rec] ----------------
__global__ void __launch_bounds__(256) k_edge2(
    const __nv_bfloat16* __restrict__ h1in,
    const int*   __restrict__ ei,
    const float* __restrict__ W2,
    const float* __restrict__ b2)
{
    extern __shared__ char smem[];
    __nv_bfloat16* A_s = (__nv_bfloat16*)(smem + E2_A);
    __nv_bfloat16* Bhi = (__nv_bfloat16*)(smem + E2_BHI);
    __nv_bfloat16* Blo = (__nv_bfloat16*)(smem + E2_BLO);

    const int tid = threadIdx.x;
    convert_B(W2, Bhi, Blo, tid);

    const int w = tid >> 5, l = tid & 31;
    const int g = l >> 2, tg = l & 3;
    const int mrow = (w >> 1) * 32, ncol = (w & 1) * 32;

    const uint4* src = reinterpret_cast<const uint4*>(h1in);

    for (int t = blockIdx.x; t < NTILES; t += EDGE_GRID) {
        const int base = t * TR;
        __syncthreads();
        // load bf16 h1 tile, BN+relu, store single plane
#pragma unroll
        for (int it = 0; it < 4; ++it) {
            int chunk = tid + it * 256;          // 1024 chunks of 8 cols
            int row = chunk >> 3, c8 = chunk & 7;
            uint4 raw = __ldg(src + (long long)(base + row) * 8 + c8);
            const uint32_t* rw = reinterpret_cast<const uint32_t*>(&raw);
            uint32_t outp[4];
#pragma unroll
            for (int p = 0; p < 4; ++p) {
                float2 hv = __bfloat1622float2(*reinterpret_cast<const __nv_bfloat162*>(&rw[p]));
                int c = c8 * 8 + p * 2;
                float2 cs = *reinterpret_cast<const float2*>(g_coef + c);
                float2 ch = *reinterpret_cast<const float2*>(g_coef + 64 + c);
                float vx = fmaxf(fmaf(hv.x, cs.x, ch.x), 0.f);
                float vy = fmaxf(fmaf(hv.y, cs.y, ch.y), 0.f);
                __nv_bfloat162 o2 = __float22bfloat162_rn(make_float2(vx, vy));
                outp[p] = *reinterpret_cast<uint32_t*>(&o2);
            }
            *reinterpret_cast<uint4*>(A_s + row * SAB + c8 * 8) =
                make_uint4(outp[0], outp[1], outp[2], outp[3]);
        }
        __syncthreads();

        float d[2][4][4];
#pragma unroll
        for (int mt = 0; mt < 2; ++mt)
#pragma unroll
            for (int nt = 0; nt < 4; ++nt)
#pragma unroll
                for (int j = 0; j < 4; ++j) d[mt][nt][j] = 0.f;

#pragma unroll
        for (int kit = 0; kit < 4; ++kit) {
            const int kb = kit * 16 + 2 * tg;
            uint32_t a[2][4], bhi[4][2], blo[4][2];
#pragma unroll
            for (int mt = 0; mt < 2; ++mt) {
                const int r = mrow + mt * 16 + g;
                a[mt][0] = ld32bf(A_s + r * SAB + kb);
                a[mt][1] = ld32bf(A_s + (r + 8) * SAB + kb);
                a[mt][2] = ld32bf(A_s + r * SAB + kb + 8);
                a[mt][3] = ld32bf(A_s + (r + 8) * SAB + kb + 8);
            }
#pragma unroll
            for (int nt = 0; nt < 4; ++nt) {
                const int n = ncol + nt * 8 + g;
                bhi[nt][0] = ld32bf(Bhi + n * SAB + kb);
                bhi[nt][1] = ld32bf(Bhi + n * SAB + kb + 8);
                blo[nt][0] = ld32bf(Blo + n * SAB + kb);
                blo[nt][1] = ld32bf(Blo + n * SAB + kb + 8);
            }
#pragma unroll
            for (int mt = 0; mt < 2; ++mt)
#pragma unroll
                for (int nt = 0; nt < 4; ++nt) {
                    MMA16816(d[mt][nt], a[mt], bhi[nt]);
                    MMA16816(d[mt][nt], a[mt], blo[nt]);
                }
        }

#pragma unroll
        for (int mt = 0; mt < 2; ++mt) {
#pragma unroll
            for (int h = 0; h < 2; ++h) {
                const int rl = mrow + mt * 16 + g + h * 8;
                const long long rr = base + rl;
                const int rec = __ldg(ei + NE + rr);
                float* dst = g_agg + (long long)rec * 64;
#pragma unroll
                for (int nt = 0; nt < 4; ++nt) {
                    const int c = ncol + nt * 8 + 2 * tg;
                    float2 bb = __ldg(reinterpret_cast<const float2*>(b2 + c));
                    red_add2(dst + c, d[mt][nt][h * 2 + 0] + bb.x,
                                      d[mt][nt][h * 2 + 1] + bb.y);
                }
            }
        }
    }
}

// ---------------- fp32x2 node-side kernels ----------------
__device__ __forceinline__ void load_W(const float* __restrict__ W, float* W_s, int tid) {
    const float4* wg = reinterpret_cast<const float4*>(W);
    float4* ws = reinterpret_cast<float4*>(W_s);
#pragma unroll
    for (int j = 0; j < 4; ++j) ws[tid + j * NT] = wg[tid + j * NT];
}
__device__ __forceinline__ float2 unpack2(unsigned long long v) {
    float2 r;
    asm("mov.b64 {%0,%1}, %2;" : "=f"(r.x), "=f"(r.y) : "l"(v));
    return r;
}
__device__ __forceinline__ void mm64x2(const float* __restrict__ A_s,
                                       const float* __restrict__ W_s,
                                       int rg, int c4, unsigned long long acc[4][4]) {
#pragma unroll 8
    for (int k = 0; k < 64; ++k) {
        const float4 b = *reinterpret_cast<const float4*>(W_s + k * 64 + c4 * 4);
        unsigned long long bd0, bd1, bd2, bd3;
        asm("mov.b64 %0,{%1,%1};" : "=l"(bd0) : "f"(b.x));
        asm("mov.b64 %0,{%1,%1};" : "=l"(bd1) : "f"(b.y));
        asm("mov.b64 %0,{%1,%1};" : "=l"(bd2) : "f"(b.z));
        asm("mov.b64 %0,{%1,%1};" : "=l"(bd3) : "f"(b.w));
        const unsigned long long* ap =
            reinterpret_cast<const unsigned long long*>(A_s + k * SA2 + rg * 8);
#pragma unroll
        for (int i = 0; i < 4; ++i) {
            unsigned long long a = ap[i];
            asm("fma.rn.f32x2 %0, %1, %2, %0;" : "+l"(acc[i][0]) : "l"(a), "l"(bd0));
            asm("fma.rn.f32x2 %0, %1, %2, %0;" : "+l"(acc[i][1]) : "l"(a), "l"(bd1));
            asm("fma.rn.f32x2 %0, %1, %2, %0;" : "+l"(acc[i][2]) : "l"(a), "l"(bd2));
            asm("fma.rn.f32x2 %0, %1, %2, %0;" : "+l"(acc[i][3]) : "l"(a), "l"(bd3));
        }
    }
}
#define ZERO_ACC2(acc) do { \
    _Pragma("unroll") for (int _i = 0; _i < 4; ++_i) { \
        acc[_i][0]=0ull; acc[_i][1]=0ull; acc[_i][2]=0ull; acc[_i][3]=0ull; } } while (0)

__device__ __forceinline__ void stat_reduce(float* buf, int tid, int rg, int c4,
                                            const float s[4], const float q[4], int off) {
    __syncthreads();
#pragma unroll
    for (int j = 0; j < 4; ++j) {
        buf[rg * 64 + c4 * 4 + j]        = s[j];
        buf[1024 + rg * 64 + c4 * 4 + j] = q[j];
    }
    __syncthreads();
    if (tid < 128) {
        int c = tid & 63, which = tid >> 6;
        float a = 0.f;
#pragma unroll
        for (int gg = 0; gg < 16; ++gg) a += buf[which * 1024 + gg * 64 + c];
        atomicAdd(&g_stats[off + which * 64 + c], a);
    }
}

__global__ void k_zero() {
    int i = blockIdx.x * blockDim.x + threadIdx.x;
    if (i < NN * 64) g_agg[i] = 0.f;
    if (i < NN)      g_cnt[i] = 0;
    if (i < 256)     g_stats[i] = 0.f;
}
__global__ void k_inv() {
    int i = blockIdx.x * blockDim.x + threadIdx.x;
    if (i < NN) g_inv[i] = 1.0f / fmaxf((float)g_cnt[i], 1.0f);
}
__global__ void k_coef(int off, float invR,
                       const float* __restrict__ gamma, const float* __restrict__ beta) {
    int c = threadIdx.x;
    float mean = g_stats[off + c] * invR;
    float ms   = g_stats[off + 64 + c] * invR;
    float var  = ms - mean * mean;
    float sc   = gamma[c] * rsqrtf(var + EPSB);
    g_coef[off + c]      = sc;
    g_coef[off + 64 + c] = beta[c] - mean * sc;
}
__global__ void k_gemm_bias(const float* __restrict__ A, int R,
                            const float* __restrict__ W,
                            const float* __restrict__ bias,
                            float* __restrict__ out) {
    extern __shared__ float smemf[];
    float* A_s = smemf;
    float* W_s = smemf + 64 * SA2;
    const int tid = threadIdx.x;
    const int base = blockIdx.x * TR;
    load_W(W, W_s, tid);
#pragma unroll
    for (int j = 0; j < 32; ++j) {
        int idx = tid + j * NT;
        int k = idx & 63, row = idx >> 6;
        int r = base + row; if (r > R - 1) r = R - 1;
        A_s[k * SA2 + row] = A[r * 64 + k];
    }
    __syncthreads();
    const int c4 = tid & 15, rg = tid >> 4;
    unsigned long long acc[4][4];
    ZERO_ACC2(acc);
    mm64x2(A_s, W_s, rg, c4, acc);
    const float4 bb = *reinterpret_cast<const float4*>(bias + c4 * 4);
#pragma unroll
    for (int i = 0; i < 4; ++i) {
        float2 p0 = unpack2(acc[i][0]), p1 = unpack2(acc[i][1]);
        float2 p2 = unpack2(acc[i][2]), p3 = unpack2(acc[i][3]);
        int r0 = base + rg * 8 + 2 * i;
        if (r0 < R)
            *reinterpret_cast<float4*>(out + r0 * 64 + c4 * 4) =
                make_float4(p0.x + bb.x, p1.x + bb.y, p2.x + bb.z, p3.x + bb.w);
        if (r0 + 1 < R)
            *reinterpret_cast<float4*>(out + (r0 + 1) * 64 + c4 * 4) =
                make_float4(p0.y + bb.x, p1.y + bb.y, p2.y + bb.z, p3.y + bb.w);
    }
}
__global__ void k_node1(const float* __restrict__ Wbot) {
    extern __shared__ float smemf[];
    float* A_s = smemf;
    float* W_s = smemf + 64 * SA2;
    const int tid = threadIdx.x;
    const int base = blockIdx.x * TR;
    load_W(Wbot, W_s, tid);
#pragma unroll
    for (int j = 0; j < 32; ++j) {
        int idx = tid + j * NT;
        int k = idx & 63, row = idx >> 6;
        int r = base + row; if (r > NN - 1) r = NN - 1;
        A_s[k * SA2 + row] = g_agg[r * 64 + k] * g_inv[r];
    }
    __syncthreads();
    const int c4 = tid & 15, rg = tid >> 4;
    unsigned long long acc[4][4];
    ZERO_ACC2(acc);
    mm64x2(A_s, W_s, rg, c4, acc);
    float s[4] = {0.f,0.f,0.f,0.f}, q[4] = {0.f,0.f,0.f,0.f};
#pragma unroll
    for (int i = 0; i < 4; ++i) {
        float2 p0 = unpack2(acc[i][0]), p1 = unpack2(acc[i][1]);
        float2 p2 = unpack2(acc[i][2]), p3 = unpack2(acc[i][3]);
        int r0 = base + rg * 8 + 2 * i;
        if (r0 < NN) {
            float4 xw = *reinterpret_cast<const float4*>(g_xw1n + r0 * 64 + c4 * 4);
            float4 v = make_float4(p0.x + xw.x, p1.x + xw.y, p2.x + xw.z, p3.x + xw.w);
            *reinterpret_cast<float4*>(g_hn + r0 * 64 + c4 * 4) = v;
            s[0] += v.x; q[0] += v.x * v.x; s[1] += v.y; q[1] += v.y * v.y;
            s[2] += v.z; q[2] += v.z * v.z; s[3] += v.w; q[3] += v.w * v.w;
        }
        if (r0 + 1 < NN) {
            float4 xw = *reinterpret_cast<const float4*>(g_xw1n + (r0 + 1) * 64 + c4 * 4);
            float4 v = make_float4(p0.y + xw.x, p1.y + xw.y, p2.y + xw.z, p3.y + xw.w);
            *reinterpret_cast<float4*>(g_hn + (r0 + 1) * 64 + c4 * 4) = v;
            s[0] += v.x; q[0] += v.x * v.x; s[1] += v.y; q[1] += v.y * v.y;
            s[2] += v.z; q[2] += v.z * v.z; s[3] += v.w; q[3] += v.w * v.w;
        }
    }
    stat_reduce(A_s, tid, rg, c4, s, q, 128);
}
__global__ void k_node2(const float* __restrict__ W2,
                        const float* __restrict__ b2,
                        float* __restrict__ out) {
    extern __shared__ float smemf[];
    float* A_s = smemf;
    float* W_s = smemf + 64 * SA2;
    const int tid = threadIdx.x;
    const int base = blockIdx.x * TR;
    load_W(W2, W_s, tid);
    const float cs = g_coef[128 + (tid & 63)];
    const float ch = g_coef[192 + (tid & 63)];
#pragma unroll
    for (int j = 0; j < 32; ++j) {
        int idx = tid + j * NT;
        int k = idx & 63, row = idx >> 6;
        int r = base + row; if (r > NN - 1) r = NN - 1;
        float v = fmaf(g_hn[r * 64 + k], cs, ch);
        A_s[k * SA2 + row] = fmaxf(v, 0.f);
    }
    __syncthreads();
    const int c4 = tid & 15, rg = tid >> 4;
    unsigned long long acc[4][4];
    ZERO_ACC2(acc);
    mm64x2(A_s, W_s, rg, c4, acc);
    const float4 bb = *reinterpret_cast<const float4*>(b2 + c4 * 4);
#pragma unroll
    for (int i = 0; i < 4; ++i) {
        float2 p0 = unpack2(acc[i][0]), p1 = unpack2(acc[i][1]);
        float2 p2 = unpack2(acc[i][2]), p3 = unpack2(acc[i][3]);
        int r0 = base + rg * 8 + 2 * i;
        if (r0 < NN)
            *reinterpret_cast<float4*>(out + r0 * 64 + c4 * 4) =
                make_float4(p0.x + bb.x, p1.x + bb.y, p2.x + bb.z, p3.x + bb.w);
        if (r0 + 1 < NN)
            *reinterpret_cast<float4*>(out + (r0 + 1) * 64 + c4 * 4) =
                make_float4(p0.y + bb.x, p1.y + bb.y, p2.y + bb.z, p3.y + bb.w);
    }
}

// ---------------- launch ----------------
extern "C" void kernel_launch(void* const* d_in, const int* in_sizes, int n_in,
                              void* d_out, int out_size) {
    const float* x   = (const float*)d_in[0];
    const int*   ei  = (const int*)d_in[1];
    const float* ea  = (const float*)d_in[2];
    const float* w1m = (const float*)d_in[5];
    const float* b1m = (const float*)d_in[6];
    const float* gm  = (const float*)d_in[7];
    const float* bm  = (const float*)d_in[8];
    const float* w2m = (const float*)d_in[9];
    const float* b2m = (const float*)d_in[10];
    const float* w1n = (const float*)d_in[11];
    const float* b1n = (const float*)d_in[12];
    const float* gn  = (const float*)d_in[13];
    const float* bn  = (const float*)d_in[14];
    const float* w2n = (const float*)d_in[15];
    const float* b2n = (const float*)d_in[16];
    float* out = (float*)d_out;

    cudaFuncSetAttribute(k_gemm_bias, cudaFuncAttributeMaxDynamicSharedMemorySize, SMEM_BYTES);
    cudaFuncSetAttribute(k_node1,     cudaFuncAttributeMaxDynamicSharedMemorySize, SMEM_BYTES);
    cudaFuncSetAttribute(k_node2,     cudaFuncAttributeMaxDynamicSharedMemorySize, SMEM_BYTES);
    cudaFuncSetAttribute(k_edge1,     cudaFuncAttributeMaxDynamicSharedMemorySize, E1_SMEM);
    cudaFuncSetAttribute(k_edge2,     cudaFuncAttributeMaxDynamicSharedMemorySize, E2_SMEM);

    float *p_xw1m, *p_xw1n;
    __nv_bfloat16* p_h1;
    cudaGetSymbolAddress((void**)&p_xw1m, g_xw1m);
    cudaGetSymbolAddress((void**)&p_xw1n, g_xw1n);
    cudaGetSymbolAddress((void**)&p_h1,   g_h1);

    const int nodeBlocks = (NN + TR - 1) / TR;

    k_zero<<<(NN * 64 + NT - 1) / NT, NT>>>();
    k_gemm_bias<<<nodeBlocks, NT, SMEM_BYTES>>>(x, NN, w1m, b1m, p_xw1m);
    k_gemm_bias<<<nodeBlocks, NT, SMEM_BYTES>>>(x, NN, w1n, b1n, p_xw1n);
    k_edge1<<<EDGE_GRID, 256, E1_SMEM>>>(ea, p_h1, ei, w1m + 64 * 64);
    k_inv<<<(NN + NT - 1) / NT, NT>>>();
    k_coef<<<1, 64>>>(0, 1.0f / (float)NE, gm, bm);
    k_edge2<<<EDGE_GRID, 256, E2_SMEM>>>(p_h1, ei, w2m, b2m);
    k_node1<<<nodeBlocks, NT, SMEM_BYTES>>>(w1n + 64 * 64);
    k_coef<<<1, 64>>>(128, 1.0f / (float)NN, gn, bn);
    k_node2<<<nodeBlocks, NT, SMEM_BYTES>>>(w2n, b2n, out);
}

// round 8
// speedup vs baseline: 1.8092x; 1.1242x over previous
#include <cuda_runtime.h>
#include <cuda_bf16.h>
#include <cstdint>

#define NN 50000
#define NE 800000
#define EPSB 1e-5f

#define TR 128
#define NTILES (NE / TR)      // 6250
#define EDGE_GRID 444         // 3 persistent CTAs/SM
#define SA2 130
#define NT 256
#define SMEM_FLOATS (64*SA2 + 64*64)
#define SMEM_BYTES  (SMEM_FLOATS * 4)

// ---- edge kernel smem (bytes) ----
#define SAB 72                // bf16 row stride
// edge1/edge2: A | Bhi | Blo | sbuf
#define E_A    0
#define E_BHI  18432
#define E_BLO  27648
#define E_SBUF 36864
#define E_SMEM 38912

// ---------------- scratch ----------------
__device__ __align__(16) float g_xw1m[NN * 64];
__device__ __align__(16) float g_xw1n[NN * 64];
__device__ __align__(16) __nv_bfloat16 g_h1[NE * 64];
__device__ __align__(16) float g_hn[NN * 64];
__device__ __align__(16) float g_agg[NN * 64];
__device__ float g_inv[NN];
__device__ int   g_cnt[NN];
__device__ float g_stats[256];
__device__ float g_coef[256];

// ---------------- helpers ----------------
__device__ __forceinline__ void red_add2(float* p, float x, float y) {
    asm volatile("red.global.add.v2.f32 [%0], {%1,%2};" :: "l"(p), "f"(x), "f"(y) : "memory");
}
#define MMA16816(d, a, b) \
    asm volatile("mma.sync.aligned.m16n8k16.row.col.f32.bf16.bf16.f32 " \
        "{%0,%1,%2,%3}, {%4,%5,%6,%7}, {%8,%9}, {%0,%1,%2,%3};" \
        : "+f"((d)[0]), "+f"((d)[1]), "+f"((d)[2]), "+f"((d)[3]) \
        : "r"((a)[0]), "r"((a)[1]), "r"((a)[2]), "r"((a)[3]), "r"((b)[0]), "r"((b)[1]))

__device__ __forceinline__ uint32_t ld32bf(const __nv_bfloat16* p) {
    return *reinterpret_cast<const uint32_t*>(p);
}
__device__ __forceinline__ void convert_B(const float* __restrict__ W,
                                          __nv_bfloat16* Bhi, __nv_bfloat16* Blo, int tid) {
#pragma unroll 4
    for (int it = 0; it < 16; ++it) {
        int idx = tid + it * 256;
        int k = idx >> 6, n = idx & 63;
        float w = __ldg(W + k * 64 + n);
        __nv_bfloat16 hi = __float2bfloat16(w);
        __nv_bfloat16 lo = __float2bfloat16(w - __bfloat162float(hi));
        Bhi[n * SAB + k] = hi;
        Blo[n * SAB + k] = lo;
    }
}

// ---------------- edge1: h1 = bf16(ea @ Wbot + xw1m[send]), fused stats + counts ----------------
__global__ void __launch_bounds__(256, 3) k_edge1(
    const float* __restrict__ ea,
    __nv_bfloat16* __restrict__ h1out,
    const int*   __restrict__ ei,
    const float* __restrict__ W)
{
    extern __shared__ char smem[];
    __nv_bfloat16* A_s = (__nv_bfloat16*)(smem + E_A);
    __nv_bfloat16* Bhi = (__nv_bfloat16*)(smem + E_BHI);
    __nv_bfloat16* Blo = (__nv_bfloat16*)(smem + E_BLO);
    float* sbuf = (float*)(smem + E_SBUF);

    const int tid = threadIdx.x;
    convert_B(W, Bhi, Blo, tid);

    const int w = tid >> 5, l = tid & 31;
    const int g = l >> 2, tg = l & 3;
    const int mrow = (w >> 1) * 32, ncol = (w & 1) * 32;

    float s8[8], q8[8];
#pragma unroll
    for (int j = 0; j < 8; ++j) { s8[j] = 0.f; q8[j] = 0.f; }

    const float4* src4 = reinterpret_cast<const float4*>(ea);

    for (int t = blockIdx.x; t < NTILES; t += EDGE_GRID) {
        const int base = t * TR;
        __syncthreads();
#pragma unroll 4
        for (int it = 0; it < 8; ++it) {
            int chunk = tid + it * 256;
            int row = chunk >> 4, c4 = chunk & 15;
            float4 v = __ldg(src4 + (long long)(base + row) * 16 + c4);
            __nv_bfloat162 b01 = __float22bfloat162_rn(make_float2(v.x, v.y));
            __nv_bfloat162 b23 = __float22bfloat162_rn(make_float2(v.z, v.w));
            *reinterpret_cast<uint2*>(A_s + row * SAB + c4 * 4) =
                make_uint2(*reinterpret_cast<uint32_t*>(&b01),
                           *reinterpret_cast<uint32_t*>(&b23));
        }
        __syncthreads();

        float d[2][4][4];
#pragma unroll
        for (int mt = 0; mt < 2; ++mt)
#pragma unroll
            for (int nt = 0; nt < 4; ++nt)
#pragma unroll
                for (int j = 0; j < 4; ++j) d[mt][nt][j] = 0.f;

#pragma unroll
        for (int kit = 0; kit < 4; ++kit) {
            const int kb = kit * 16 + 2 * tg;
            uint32_t a[2][4], bhi[4][2], blo[4][2];
#pragma unroll
            for (int mt = 0; mt < 2; ++mt) {
                const int r = mrow + mt * 16 + g;
                a[mt][0] = ld32bf(A_s + r * SAB + kb);
                a[mt][1] = ld32bf(A_s + (r + 8) * SAB + kb);
                a[mt][2] = ld32bf(A_s + r * SAB + kb + 8);
                a[mt][3] = ld32bf(A_s + (r + 8) * SAB + kb + 8);
            }
#pragma unroll
            for (int nt = 0; nt < 4; ++nt) {
                const int n = ncol + nt * 8 + g;
                bhi[nt][0] = ld32bf(Bhi + n * SAB + kb);
                bhi[nt][1] = ld32bf(Bhi + n * SAB + kb + 8);
                blo[nt][0] = ld32bf(Blo + n * SAB + kb);
                blo[nt][1] = ld32bf(Blo + n * SAB + kb + 8);
            }
#pragma unroll
            for (int mt = 0; mt < 2; ++mt)
#pragma unroll
                for (int nt = 0; nt < 4; ++nt) {
                    MMA16816(d[mt][nt], a[mt], bhi[nt]);
                    MMA16816(d[mt][nt], a[mt], blo[nt]);
                }
        }

#pragma unroll
        for (int mt = 0; mt < 2; ++mt) {
#pragma unroll
            for (int h = 0; h < 2; ++h) {
                const int rl = mrow + mt * 16 + g + h * 8;
                const long long rr = base + rl;
                const int snd = __ldg(ei + rr);
                if (tg == 0 && (w & 1) == 0)
                    atomicAdd(&g_cnt[__ldg(ei + NE + rr)], 1);
                const float2* xw = reinterpret_cast<const float2*>(g_xw1m + (long long)snd * 64);
#pragma unroll
                for (int nt = 0; nt < 4; ++nt) {
                    const int c = ncol + nt * 8 + 2 * tg;
                    float2 xv = __ldg(xw + (c >> 1));
                    float vx = d[mt][nt][h * 2 + 0] + xv.x;
                    float vy = d[mt][nt][h * 2 + 1] + xv.y;
                    __nv_bfloat162 hv = __float22bfloat162_rn(make_float2(vx, vy));
                    *reinterpret_cast<uint32_t*>(h1out + rr * 64 + c) =
                        *reinterpret_cast<uint32_t*>(&hv);
                    s8[nt * 2 + 0] += vx; q8[nt * 2 + 0] += vx * vx;
                    s8[nt * 2 + 1] += vy; q8[nt * 2 + 1] += vy * vy;
                }
            }
        }
    }

    // final BN-stat reduction (once per CTA)
#pragma unroll
    for (int off = 4; off < 32; off <<= 1) {
#pragma unroll
        for (int j = 0; j < 8; ++j) {
            s8[j] += __shfl_xor_sync(0xFFFFFFFFu, s8[j], off);
            q8[j] += __shfl_xor_sync(0xFFFFFFFFu, q8[j], off);
        }
    }
    __syncthreads();
    if (g == 0) {
        const int slot = w >> 1;
#pragma unroll
        for (int nt = 0; nt < 4; ++nt) {
            const int c = ncol + nt * 8 + 2 * tg;
            *reinterpret_cast<float2*>(sbuf + slot * 64 + c) =
                make_float2(s8[nt * 2], s8[nt * 2 + 1]);
            *reinterpret_cast<float2*>(sbuf + (4 + slot) * 64 + c) =
                make_float2(q8[nt * 2], q8[nt * 2 + 1]);
        }
    }
    __syncthreads();
    if (tid < 128) {
        const int stat = tid >> 6, c = tid & 63;
        float a = sbuf[(stat * 4 + 0) * 64 + c] + sbuf[(stat * 4 + 1) * 64 + c]
                + sbuf[(stat * 4 + 2) * 64 + c] + sbuf[(stat * 4 + 3) * 64 + c];
        atomicAdd(&g_stats[stat * 64 + c], a);
    }
}

// ---------------- edge2: relu(BN(h1)) @ W2 + b2 -> red.add g_agg[rec] ----------------
__global__ void __launch_bounds__(256, 3) k_edge2(
    const __nv_bfloat16* __restrict__ h1in,
    const int*   __restrict__ ei,
    const float* __restrict__ W2,
    const float* __restrict__ b2)
{
    extern __shared__ char smem[];
    __nv_bfloat16* A_s = (__nv_bfloat16*)(smem + E_A);
    __nv_bfloat16* Bhi = (__nv_bfloat16*)(smem + E_BHI);
    __nv_bfloat16* Blo = (__nv_bfloat16*)(smem + E_BLO);

    const int tid = threadIdx.x;
    convert_B(W2, Bhi, Blo, tid);

    const int w = tid >> 5, l = tid & 31;
    const int g = l >> 2, tg = l & 3;
    const int mrow = (w >> 1) * 32, ncol = (w & 1) * 32;

    const uint4* src = reinterpret_cast<const uint4*>(h1in);

    for (int t = blockIdx.x; t < NTILES; t += EDGE_GRID) {
        const int base = t * TR;
        __syncthreads();
#pragma unroll
        for (int it = 0; it < 4; ++it) {
            int chunk = tid + it * 256;
            int row = chunk >> 3, c8 = chunk & 7;
            uint4 raw = __ldg(src + (long long)(base + row) * 8 + c8);
            const uint32_t* rw = reinterpret_cast<const uint32_t*>(&raw);
            uint32_t outp[4];
#pragma unroll
            for (int p = 0; p < 4; ++p) {
                float2 hv = __bfloat1622float2(*reinterpret_cast<const __nv_bfloat162*>(&rw[p]));
                int c = c8 * 8 + p * 2;
                float2 cs = *reinterpret_cast<const float2*>(g_coef + c);
                float2 ch = *reinterpret_cast<const float2*>(g_coef + 64 + c);
                float vx = fmaxf(fmaf(hv.x, cs.x, ch.x), 0.f);
                float vy = fmaxf(fmaf(hv.y, cs.y, ch.y), 0.f);
                __nv_bfloat162 o2 = __float22bfloat162_rn(make_float2(vx, vy));
                outp[p] = *reinterpret_cast<uint32_t*>(&o2);
            }
            *reinterpret_cast<uint4*>(A_s + row * SAB + c8 * 8) =
                make_uint4(outp[0], outp[1], outp[2], outp[3]);
        }
        __syncthreads();

        float d[2][4][4];
#pragma unroll
        for (int mt = 0; mt < 2; ++mt)
#pragma unroll
            for (int nt = 0; nt < 4; ++nt)
#pragma unroll
                for (int j = 0; j < 4; ++j) d[mt][nt][j] = 0.f;

#pragma unroll
        for (int kit = 0; kit < 4; ++kit) {
            const int kb = kit * 16 + 2 * tg;
            uint32_t a[2][4], bhi[4][2], blo[4][2];
#pragma unroll
            for (int mt = 0; mt < 2; ++mt) {
                const int r = mrow + mt * 16 + g;
                a[mt][0] = ld32bf(A_s + r * SAB + kb);
                a[mt][1] = ld32bf(A_s + (r + 8) * SAB + kb);
                a[mt][2] = ld32bf(A_s + r * SAB + kb + 8);
                a[mt][3] = ld32bf(A_s + (r + 8) * SAB + kb + 8);
            }
#pragma unroll
            for (int nt = 0; nt < 4; ++nt) {
                const int n = ncol + nt * 8 + g;
                bhi[nt][0] = ld32bf(Bhi + n * SAB + kb);
                bhi[nt][1] = ld32bf(Bhi + n * SAB + kb + 8);
                blo[nt][0] = ld32bf(Blo + n * SAB + kb);
                blo[nt][1] = ld32bf(Blo + n * SAB + kb + 8);
            }
#pragma unroll
            for (int mt = 0; mt < 2; ++mt)
#pragma unroll
                for (int nt = 0; nt < 4; ++nt) {
                    MMA16816(d[mt][nt], a[mt], bhi[nt]);
                    MMA16816(d[mt][nt], a[mt], blo[nt]);
                }
        }

#pragma unroll
        for (int mt = 0; mt < 2; ++mt) {
#pragma unroll
            for (int h = 0; h < 2; ++h) {
                const int rl = mrow + mt * 16 + g + h * 8;
                const long long rr = base + rl;
                const int rec = __ldg(ei + NE + rr);
                float* dst = g_agg + (long long)rec * 64;
#pragma unroll
                for (int nt = 0; nt < 4; ++nt) {
                    const int c = ncol + nt * 8 + 2 * tg;
                    float2 bb = __ldg(reinterpret_cast<const float2*>(b2 + c));
                    red_add2(dst + c, d[mt][nt][h * 2 + 0] + bb.x,
                                      d[mt][nt][h * 2 + 1] + bb.y);
                }
            }
        }
    }
}

// ---------------- fp32x2 node-side kernels ----------------
__device__ __forceinline__ void load_W(const float* __restrict__ W, float* W_s, int tid) {
    const float4* wg = reinterpret_cast<const float4*>(W);
    float4* ws = reinterpret_cast<float4*>(W_s);
#pragma unroll
    for (int j = 0; j < 4; ++j) ws[tid + j * NT] = wg[tid + j * NT];
}
__device__ __forceinline__ float2 unpack2(unsigned long long v) {
    float2 r;
    asm("mov.b64 {%0,%1}, %2;" : "=f"(r.x), "=f"(r.y) : "l"(v));
    return r;
}
__device__ __forceinline__ void mm64x2(const float* __restrict__ A_s,
                                       const float* __restrict__ W_s,
                                       int rg, int c4, unsigned long long acc[4][4]) {
#pragma unroll 8
    for (int k = 0; k < 64; ++k) {
        const float4 b = *reinterpret_cast<const float4*>(W_s + k * 64 + c4 * 4);
        unsigned long long bd0, bd1, bd2, bd3;
        asm("mov.b64 %0,{%1,%1};" : "=l"(bd0) : "f"(b.x));
        asm("mov.b64 %0,{%1,%1};" : "=l"(bd1) : "f"(b.y));
        asm("mov.b64 %0,{%1,%1};" : "=l"(bd2) : "f"(b.z));
        asm("mov.b64 %0,{%1,%1};" : "=l"(bd3) : "f"(b.w));
        const unsigned long long* ap =
            reinterpret_cast<const unsigned long long*>(A_s + k * SA2 + rg * 8);
#pragma unroll
        for (int i = 0; i < 4; ++i) {
            unsigned long long a = ap[i];
            asm("fma.rn.f32x2 %0, %1, %2, %0;" : "+l"(acc[i][0]) : "l"(a), "l"(bd0));
            asm("fma.rn.f32x2 %0, %1, %2, %0;" : "+l"(acc[i][1]) : "l"(a), "l"(bd1));
            asm("fma.rn.f32x2 %0, %1, %2, %0;" : "+l"(acc[i][2]) : "l"(a), "l"(bd2));
            asm("fma.rn.f32x2 %0, %1, %2, %0;" : "+l"(acc[i][3]) : "l"(a), "l"(bd3));
        }
    }
}
#define ZERO_ACC2(acc) do { \
    _Pragma("unroll") for (int _i = 0; _i < 4; ++_i) { \
        acc[_i][0]=0ull; acc[_i][1]=0ull; acc[_i][2]=0ull; acc[_i][3]=0ull; } } while (0)

__device__ __forceinline__ void stat_reduce(float* buf, int tid, int rg, int c4,
                                            const float s[4], const float q[4], int off) {
    __syncthreads();
#pragma unroll
    for (int j = 0; j < 4; ++j) {
        buf[rg * 64 + c4 * 4 + j]        = s[j];
        buf[1024 + rg * 64 + c4 * 4 + j] = q[j];
    }
    __syncthreads();
    if (tid < 128) {
        int c = tid & 63, which = tid >> 6;
        float a = 0.f;
#pragma unroll
        for (int gg = 0; gg < 16; ++gg) a += buf[which * 1024 + gg * 64 + c];
        atomicAdd(&g_stats[off + which * 64 + c], a);
    }
}

__global__ void k_zero() {
    int i = blockIdx.x * blockDim.x + threadIdx.x;
    if (i < NN * 64) g_agg[i] = 0.f;
    if (i < NN)      g_cnt[i] = 0;
    if (i < 256)     g_stats[i] = 0.f;
}
__global__ void k_inv() {
    int i = blockIdx.x * blockDim.x + threadIdx.x;
    if (i < NN) g_inv[i] = 1.0f / fmaxf((float)g_cnt[i], 1.0f);
}
__global__ void k_coef(int off, float invR,
                       const float* __restrict__ gamma, const float* __restrict__ beta) {
    int c = threadIdx.x;
    float mean = g_stats[off + c] * invR;
    float ms   = g_stats[off + 64 + c] * invR;
    float var  = ms - mean * mean;
    float sc   = gamma[c] * rsqrtf(var + EPSB);
    g_coef[off + c]      = sc;
    g_coef[off + 64 + c] = beta[c] - mean * sc;
}
__global__ void k_gemm_bias(const float* __restrict__ A, int R,
                            const float* __restrict__ W,
                            const float* __restrict__ bias,
                            float* __restrict__ out) {
    extern __shared__ float smemf[];
    float* A_s = smemf;
    float* W_s = smemf + 64 * SA2;
    const int tid = threadIdx.x;
    const int base = blockIdx.x * TR;
    load_W(W, W_s, tid);
#pragma unroll
    for (int j = 0; j < 32; ++j) {
        int idx = tid + j * NT;
        int k = idx & 63, row = idx >> 6;
        int r = base + row; if (r > R - 1) r = R - 1;
        A_s[k * SA2 + row] = A[r * 64 + k];
    }
    __syncthreads();
    const int c4 = tid & 15, rg = tid >> 4;
    unsigned long long acc[4][4];
    ZERO_ACC2(acc);
    mm64x2(A_s, W_s, rg, c4, acc);
    const float4 bb = *reinterpret_cast<const float4*>(bias + c4 * 4);
#pragma unroll
    for (int i = 0; i < 4; ++i) {
        float2 p0 = unpack2(acc[i][0]), p1 = unpack2(acc[i][1]);
        float2 p2 = unpack2(acc[i][2]), p3 = unpack2(acc[i][3]);
        int r0 = base + rg * 8 + 2 * i;
        if (r0 < R)
            *reinterpret_cast<float4*>(out + r0 * 64 + c4 * 4) =
                make_float4(p0.x + bb.x, p1.x + bb.y, p2.x + bb.z, p3.x + bb.w);
        if (r0 + 1 < R)
            *reinterpret_cast<float4*>(out + (r0 + 1) * 64 + c4 * 4) =
                make_float4(p0.y + bb.x, p1.y + bb.y, p2.y + bb.z, p3.y + bb.w);
    }
}
__global__ void k_node1(const float* __restrict__ Wbot) {
    extern __shared__ float smemf[];
    float* A_s = smemf;
    float* W_s = smemf + 64 * SA2;
    const int tid = threadIdx.x;
    const int base = blockIdx.x * TR;
    load_W(Wbot, W_s, tid);
#pragma unroll
    for (int j = 0; j < 32; ++j) {
        int idx = tid + j * NT;
        int k = idx & 63, row = idx >> 6;
        int r = base + row; if (r > NN - 1) r = NN - 1;
        A_s[k * SA2 + row] = g_agg[r * 64 + k] * g_inv[r];
    }
    __syncthreads();
    const int c4 = tid & 15, rg = tid >> 4;
    unsigned long long acc[4][4];
    ZERO_ACC2(acc);
    mm64x2(A_s, W_s, rg, c4, acc);
    float s[4] = {0.f,0.f,0.f,0.f}, q[4] = {0.f,0.f,0.f,0.f};
#pragma unroll
    for (int i = 0; i < 4; ++i) {
        float2 p0 = unpack2(acc[i][0]), p1 = unpack2(acc[i][1]);
        float2 p2 = unpack2(acc[i][2]), p3 = unpack2(acc[i][3]);
        int r0 = base + rg * 8 + 2 * i;
        if (r0 < NN) {
            float4 xw = *reinterpret_cast<const float4*>(g_xw1n + r0 * 64 + c4 * 4);
            float4 v = make_float4(p0.x + xw.x, p1.x + xw.y, p2.x + xw.z, p3.x + xw.w);
            *reinterpret_cast<float4*>(g_hn + r0 * 64 + c4 * 4) = v;
            s[0] += v.x; q[0] += v.x * v.x; s[1] += v.y; q[1] += v.y * v.y;
            s[2] += v.z; q[2] += v.z * v.z; s[3] += v.w; q[3] += v.w * v.w;
        }
        if (r0 + 1 < NN) {
            float4 xw = *reinterpret_cast<const float4*>(g_xw1n + (r0 + 1) * 64 + c4 * 4);
            float4 v = make_float4(p0.y + xw.x, p1.y + xw.y, p2.y + xw.z, p3.y + xw.w);
            *reinterpret_cast<float4*>(g_hn + (r0 + 1) * 64 + c4 * 4) = v;
            s[0] += v.x; q[0] += v.x * v.x; s[1] += v.y; q[1] += v.y * v.y;
            s[2] += v.z; q[2] += v.z * v.z; s[3] += v.w; q[3] += v.w * v.w;
        }
    }
    stat_reduce(A_s, tid, rg, c4, s, q, 128);
}
__global__ void k_node2(const float* __restrict__ W2,
                        const float* __restrict__ b2,
                        float* __restrict__ out) {
    extern __shared__ float smemf[];
    float* A_s = smemf;
    float* W_s = smemf + 64 * SA2;
    const int tid = threadIdx.x;
    const int base = blockIdx.x * TR;
    load_W(W2, W_s, tid);
    const float cs = g_coef[128 + (tid & 63)];
    const float ch = g_coef[192 + (tid & 63)];
#pragma unroll
    for (int j = 0; j < 32; ++j) {
        int idx = tid + j * NT;
        int k = idx & 63, row = idx >> 6;
        int r = base + row; if (r > NN - 1) r = NN - 1;
        float v = fmaf(g_hn[r * 64 + k], cs, ch);
        A_s[k * SA2 + row] = fmaxf(v, 0.f);
    }
    __syncthreads();
    const int c4 = tid & 15, rg = tid >> 4;
    unsigned long long acc[4][4];
    ZERO_ACC2(acc);
    mm64x2(A_s, W_s, rg, c4, acc);
    const float4 bb = *reinterpret_cast<const float4*>(b2 + c4 * 4);
#pragma unroll
    for (int i = 0; i < 4; ++i) {
        float2 p0 = unpack2(acc[i][0]), p1 = unpack2(acc[i][1]);
        float2 p2 = unpack2(acc[i][2]), p3 = unpack2(acc[i][3]);
        int r0 = base + rg * 8 + 2 * i;
        if (r0 < NN)
            *reinterpret_cast<float4*>(out + r0 * 64 + c4 * 4) =
                make_float4(p0.x + bb.x, p1.x + bb.y, p2.x + bb.z, p3.x + bb.w);
        if (r0 + 1 < NN)
            *reinterpret_cast<float4*>(out + (r0 + 1) * 64 + c4 * 4) =
                make_float4(p0.y + bb.x, p1.y + bb.y, p2.y + bb.z, p3.y + bb.w);
    }
}

// ---------------- launch ----------------
extern "C" void kernel_launch(void* const* d_in, const int* in_sizes, int n_in,
                              void* d_out, int out_size) {
    const float* x   = (const float*)d_in[0];
    const int*   ei  = (const int*)d_in[1];
    const float* ea  = (const float*)d_in[2];
    const float* w1m = (const float*)d_in[5];
    const float* b1m = (const float*)d_in[6];
    const float* gm  = (const float*)d_in[7];
    const float* bm  = (const float*)d_in[8];
    const float* w2m = (const float*)d_in[9];
    const float* b2m = (const float*)d_in[10];
    const float* w1n = (const float*)d_in[11];
    const float* b1n = (const float*)d_in[12];
    const float* gn  = (const float*)d_in[13];
    const float* bn  = (const float*)d_in[14];
    const float* w2n = (const float*)d_in[15];
    const float* b2n = (const float*)d_in[16];
    float* out = (float*)d_out;

    cudaFuncSetAttribute(k_gemm_bias, cudaFuncAttributeMaxDynamicSharedMemorySize, SMEM_BYTES);
    cudaFuncSetAttribute(k_node1,     cudaFuncAttributeMaxDynamicSharedMemorySize, SMEM_BYTES);
    cudaFuncSetAttribute(k_node2,     cudaFuncAttributeMaxDynamicSharedMemorySize, SMEM_BYTES);
    cudaFuncSetAttribute(k_edge1,     cudaFuncAttributeMaxDynamicSharedMemorySize, E_SMEM);
    cudaFuncSetAttribute(k_edge2,     cudaFuncAttributeMaxDynamicSharedMemorySize, E_SMEM);

    float *p_xw1m, *p_xw1n;
    __nv_bfloat16* p_h1;
    cudaGetSymbolAddress((void**)&p_xw1m, g_xw1m);
    cudaGetSymbolAddress((void**)&p_xw1n, g_xw1n);
    cudaGetSymbolAddress((void**)&p_h1,   g_h1);

    const int nodeBlocks = (NN + TR - 1) / TR;

    k_zero<<<(NN * 64 + NT - 1) / NT, NT>>>();
    k_gemm_bias<<<nodeBlocks, NT, SMEM_BYTES>>>(x, NN, w1m, b1m, p_xw1m);
    k_gemm_bias<<<nodeBlocks, NT, SMEM_BYTES>>>(x, NN, w1n, b1n, p_xw1n);
    k_edge1<<<EDGE_GRID, 256, E_SMEM>>>(ea, p_h1, ei, w1m + 64 * 64);
    k_inv<<<(NN + NT - 1) / NT, NT>>>();
    k_coef<<<1, 64>>>(0, 1.0f / (float)NE, gm, bm);
    k_edge2<<<EDGE_GRID, 256, E_SMEM>>>(p_h1, ei, w2m, b2m);
    k_node1<<<nodeBlocks, NT, SMEM_BYTES>>>(w1n + 64 * 64);
    k_coef<<<1, 64>>>(128, 1.0f / (float)NN, gn, bn);
    k_node2<<<nodeBlocks, NT, SMEM_BYTES>>>(w2n, b2n, out);
}